// round 3
// baseline (speedup 1.0000x reference)
#include <cuda_runtime.h>
#include <math.h>
#include <float.h>

#define B_    32
#define L_    1024
#define D_    512
#define TOPK_ 13

// ---------------- scratch (static device globals; no allocation) ----------------
__device__ float g_q[B_*L_*D_];
__device__ float g_k[B_*L_*D_];
__device__ float g_v[B_*L_*D_];
__device__ float g_G[(size_t)B_*L_*L_];
__device__ float g_corr[B_*L_];
__device__ int   g_delay[B_*TOPK_];
__device__ float g_w[B_*TOPK_];
__device__ float g_agg[B_*L_*D_];
__device__ float g_x1[B_*L_*D_];
__device__ float g_s1[B_*L_*D_];
__device__ float g_x2[B_*L_*D_];

// ---------------- generic tiled SGEMM: C = A*B (+bias)(+res), optional B-transpose,
// optional batching via strides. BM=BN=128, BK=16, 256 threads, 8x8 per thread.
template<bool TB>
__global__ __launch_bounds__(256, 2)
void sgemm_kernel(const float* __restrict__ A, const float* __restrict__ Bm,
                  const float* __restrict__ bias, const float* __restrict__ res,
                  float* __restrict__ C, int N, int K,
                  size_t sA, size_t sB, size_t sC)
{
    __shared__ float As[16][128];
    __shared__ float Bs[16][128];

    const int bz = blockIdx.z;
    A  += (size_t)bz * sA;
    Bm += (size_t)bz * sB;
    C  += (size_t)bz * sC;

    const int tid = threadIdx.x;
    const int m0  = blockIdx.y * 128;
    const int n0  = blockIdx.x * 128;

    const int tx = tid & 15;       // 16 col groups
    const int ty = tid >> 4;       // 16 row groups

    float acc[8][8];
    #pragma unroll
    for (int i = 0; i < 8; i++)
        #pragma unroll
        for (int j = 0; j < 8; j++) acc[i][j] = 0.0f;

    const int arow = tid >> 2;           // 0..63
    const int acol = (tid & 3) << 2;     // 0,4,8,12
    const int brow = tid >> 5;           // 0..7
    const int bcol = (tid & 31) << 2;    // 0..124

    for (int k0 = 0; k0 < K; k0 += 16) {
        // A tile (transposed into smem: As[k][m])
        #pragma unroll
        for (int r = 0; r < 128; r += 64) {
            float4 t = *(const float4*)&A[(size_t)(m0 + arow + r)*K + k0 + acol];
            As[acol+0][arow+r] = t.x;
            As[acol+1][arow+r] = t.y;
            As[acol+2][arow+r] = t.z;
            As[acol+3][arow+r] = t.w;
        }
        if (TB) {
            // B accessed as B[j][k] (NT): load like A tile
            #pragma unroll
            for (int r = 0; r < 128; r += 64) {
                float4 t = *(const float4*)&Bm[(size_t)(n0 + arow + r)*K + k0 + acol];
                Bs[acol+0][arow+r] = t.x;
                Bs[acol+1][arow+r] = t.y;
                Bs[acol+2][arow+r] = t.z;
                Bs[acol+3][arow+r] = t.w;
            }
        } else {
            // B row-major [k][n]
            #pragma unroll
            for (int r = 0; r < 16; r += 8) {
                *(float4*)&Bs[brow + r][bcol] =
                    *(const float4*)&Bm[(size_t)(k0 + brow + r)*N + n0 + bcol];
            }
        }
        __syncthreads();

        #pragma unroll
        for (int kk = 0; kk < 16; kk++) {
            float av[8], bvv[8];
            *(float4*)&av[0]  = *(const float4*)&As[kk][ty*8];
            *(float4*)&av[4]  = *(const float4*)&As[kk][ty*8+4];
            *(float4*)&bvv[0] = *(const float4*)&Bs[kk][tx*8];
            *(float4*)&bvv[4] = *(const float4*)&Bs[kk][tx*8+4];
            #pragma unroll
            for (int i = 0; i < 8; i++)
                #pragma unroll
                for (int j = 0; j < 8; j++)
                    acc[i][j] = fmaf(av[i], bvv[j], acc[i][j]);
        }
        __syncthreads();
    }

    // epilogue
    float bsv[8];
    #pragma unroll
    for (int j = 0; j < 8; j++)
        bsv[j] = bias ? bias[n0 + tx*8 + j] : 0.0f;

    #pragma unroll
    for (int i = 0; i < 8; i++) {
        const int row = m0 + ty*8 + i;
        const size_t base = (size_t)row * N + n0 + tx*8;
        #pragma unroll
        for (int jj = 0; jj < 8; jj += 4) {
            float4 o;
            o.x = acc[i][jj+0] + bsv[jj+0];
            o.y = acc[i][jj+1] + bsv[jj+1];
            o.z = acc[i][jj+2] + bsv[jj+2];
            o.w = acc[i][jj+3] + bsv[jj+3];
            if (res) {
                float4 rr = *(const float4*)&res[base + jj];
                o.x += rr.x; o.y += rr.y; o.z += rr.z; o.w += rr.w;
            }
            *(float4*)&C[base + jj] = o;
        }
    }
}

// ---------------- diagonal reduce:
// corr[b,tau] = (1/D) * sum_t G[b][(t+tau)%L][t]  ==  (1/D) * sum_r G[b][r][(r-tau)%L]
// (correlation theorem: irfft(rfft(q)*conj(rfft(k)))[tau] = sum_t q[(t+tau)%L]*k[t])
__global__ void diag_reduce_kernel(const float* __restrict__ G, float* __restrict__ corr)
{
    int gid  = blockIdx.x * blockDim.x + threadIdx.x;
    int warp = gid >> 5;
    int lane = gid & 31;
    if (warp >= B_ * L_) return;
    int b   = warp >> 10;
    int tau = warp & (L_ - 1);
    const float* Gb = G + (size_t)b * L_ * L_;
    float s = 0.0f;
    #pragma unroll 4
    for (int r = lane; r < L_; r += 32)
        s += Gb[(size_t)r * L_ + ((r - tau + L_) & (L_ - 1))];
    #pragma unroll
    for (int o = 16; o > 0; o >>= 1)
        s += __shfl_down_sync(0xffffffffu, s, o);
    if (lane == 0) corr[warp] = s * (1.0f / (float)D_);
}

// ---------------- top-13 + softmax, one block per batch
__global__ void topk_softmax_kernel(const float* __restrict__ corr,
                                    int* __restrict__ delays, float* __restrict__ w)
{
    const int b   = blockIdx.x;
    const int tid = threadIdx.x;     // 256 threads
    __shared__ float vals[L_];
    __shared__ float rv[256];
    __shared__ int   ri[256];
    __shared__ float topv[TOPK_];
    __shared__ int   topi[TOPK_];

    for (int i = tid; i < L_; i += 256) vals[i] = corr[b * L_ + i];
    __syncthreads();

    for (int sel = 0; sel < TOPK_; sel++) {
        float bv = -FLT_MAX;
        int   bi = 1 << 30;
        for (int i = tid; i < L_; i += 256) {
            float v = vals[i];
            if (v > bv || (v == bv && i < bi)) { bv = v; bi = i; }
        }
        rv[tid] = bv; ri[tid] = bi;
        __syncthreads();
        for (int s = 128; s > 0; s >>= 1) {
            if (tid < s) {
                if (rv[tid+s] > rv[tid] || (rv[tid+s] == rv[tid] && ri[tid+s] < ri[tid])) {
                    rv[tid] = rv[tid+s]; ri[tid] = ri[tid+s];
                }
            }
            __syncthreads();
        }
        if (tid == 0) {
            topv[sel] = rv[0];
            topi[sel] = ri[0];
            vals[ri[0]] = -FLT_MAX;
        }
        __syncthreads();
    }

    if (tid == 0) {
        float mx = topv[0];
        float e[TOPK_], se = 0.0f;
        #pragma unroll
        for (int i = 0; i < TOPK_; i++) { e[i] = expf(topv[i] - mx); se += e[i]; }
        float inv = 1.0f / se;
        #pragma unroll
        for (int i = 0; i < TOPK_; i++) {
            w[b*TOPK_ + i]      = e[i] * inv;
            delays[b*TOPK_ + i] = topi[i];
        }
    }
}

// ---------------- aggregation: agg[b,t,:] = sum_i w_i * V[b,(t+d_i)%L,:]
__global__ void aggregate_kernel(const float* __restrict__ V,
                                 const int* __restrict__ delays,
                                 const float* __restrict__ w,
                                 float* __restrict__ Out)
{
    const int t = blockIdx.x;
    const int b = blockIdx.y;
    const int c = threadIdx.x;   // 128 threads -> float4 over D=512
    __shared__ int   sd[TOPK_];
    __shared__ float sw[TOPK_];
    if (c < TOPK_) { sd[c] = delays[b*TOPK_ + c]; sw[c] = w[b*TOPK_ + c]; }
    __syncthreads();

    const float4* V4 = (const float4*)V;
    float4 acc = make_float4(0.f, 0.f, 0.f, 0.f);
    #pragma unroll
    for (int i = 0; i < TOPK_; i++) {
        int row = (t + sd[i]) & (L_ - 1);
        float4 vv = V4[((size_t)(b * L_ + row) * (D_/4)) + c];
        float wi = sw[i];
        acc.x = fmaf(wi, vv.x, acc.x);
        acc.y = fmaf(wi, vv.y, acc.y);
        acc.z = fmaf(wi, vv.z, acc.z);
        acc.w = fmaf(wi, vv.w, acc.w);
    }
    ((float4*)Out)[((size_t)(b * L_ + t) * (D_/4)) + c] = acc;
}

// ---------------- season = X - moving_average(X, 25) (TF SAME, count-excluding-pad)
__global__ void movavg_sub_kernel(const float* __restrict__ X, float* __restrict__ Out)
{
    const int t = blockIdx.x;
    const int b = blockIdx.y;
    const int c = threadIdx.x;   // 128 threads, float4
    const int lo = max(t - 12, 0);
    const int hi = min(t + 12, L_ - 1);
    const float4* X4 = (const float4*)X;
    float4 s = make_float4(0.f, 0.f, 0.f, 0.f);
    for (int ss = lo; ss <= hi; ss++) {
        float4 v = X4[((size_t)(b * L_ + ss) * (D_/4)) + c];
        s.x += v.x; s.y += v.y; s.z += v.z; s.w += v.w;
    }
    float inv = 1.0f / (float)(hi - lo + 1);
    float4 xv = X4[((size_t)(b * L_ + t) * (D_/4)) + c];
    float4 o;
    o.x = xv.x - s.x * inv;
    o.y = xv.y - s.y * inv;
    o.z = xv.z - s.z * inv;
    o.w = xv.w - s.w * inv;
    ((float4*)Out)[((size_t)(b * L_ + t) * (D_/4)) + c] = o;
}

// ---------------- host launch ----------------
extern "C" void kernel_launch(void* const* d_in, const int* in_sizes, int n_in,
                              void* d_out, int out_size)
{
    const float* x  = (const float*)d_in[0];
    const float* Wq = (const float*)d_in[1];
    const float* bq = (const float*)d_in[2];
    const float* Wk = (const float*)d_in[3];
    const float* bk = (const float*)d_in[4];
    const float* Wv = (const float*)d_in[5];
    const float* bv = (const float*)d_in[6];
    const float* Wo = (const float*)d_in[7];
    const float* bo = (const float*)d_in[8];
    const float* Wd = (const float*)d_in[9];
    const float* bd = (const float*)d_in[10];
    float* out = (float*)d_out;

    float *q, *k, *v, *G, *corr, *w, *agg, *x1, *s1, *x2;
    int* dl;
    cudaGetSymbolAddress((void**)&q,    g_q);
    cudaGetSymbolAddress((void**)&k,    g_k);
    cudaGetSymbolAddress((void**)&v,    g_v);
    cudaGetSymbolAddress((void**)&G,    g_G);
    cudaGetSymbolAddress((void**)&corr, g_corr);
    cudaGetSymbolAddress((void**)&dl,   g_delay);
    cudaGetSymbolAddress((void**)&w,    g_w);
    cudaGetSymbolAddress((void**)&agg,  g_agg);
    cudaGetSymbolAddress((void**)&x1,   g_x1);
    cudaGetSymbolAddress((void**)&s1,   g_s1);
    cudaGetSymbolAddress((void**)&x2,   g_x2);

    dim3 t256(256);
    dim3 gproj(D_/128, (B_*L_)/128, 1);      // (4, 256)
    dim3 ggram(L_/128, L_/128, B_);          // (8, 8, 32)
    dim3 gld(L_, B_);

    // Q/K/V projections
    sgemm_kernel<false><<<gproj, t256>>>(x, Wq, bq, nullptr, q, D_, D_, 0, 0, 0);
    sgemm_kernel<false><<<gproj, t256>>>(x, Wk, bk, nullptr, k, D_, D_, 0, 0, 0);
    sgemm_kernel<false><<<gproj, t256>>>(x, Wv, bv, nullptr, v, D_, D_, 0, 0, 0);

    // batched Gram: G[b] = Q[b] @ K[b]^T
    sgemm_kernel<true><<<ggram, t256>>>(q, k, nullptr, nullptr, G, L_, D_,
                                        (size_t)L_*D_, (size_t)L_*D_, (size_t)L_*L_);

    // circular-diagonal reduction -> mean_corr
    {
        int warps = B_ * L_;
        int threads = 256;
        int blocks = (warps * 32 + threads - 1) / threads;
        diag_reduce_kernel<<<blocks, threads>>>(G, corr);
    }

    // top-13 + softmax per batch
    topk_softmax_kernel<<<B_, 256>>>(corr, dl, w);

    // delay aggregation of V
    aggregate_kernel<<<gld, 128>>>(v, dl, w, agg);

    // ac = agg @ Wo + bo; x1 = ac + x  (residual fused)
    sgemm_kernel<false><<<gproj, t256>>>(agg, Wo, bo, x, x1, D_, D_, 0, 0, 0);

    // series decomp 1: s1 = x1 - movavg(x1)
    movavg_sub_kernel<<<gld, 128>>>(x1, s1);

    // x2 = s1 @ Wd + bd + s1 (residual fused)
    sgemm_kernel<false><<<gproj, t256>>>(s1, Wd, bd, s1, x2, D_, D_, 0, 0, 0);

    // series decomp 2 -> output
    movavg_sub_kernel<<<gld, 128>>>(x2, out);
}

// round 4
// speedup vs baseline: 1.0070x; 1.0070x over previous
#include <cuda_runtime.h>
#include <math.h>
#include <float.h>

#define B_    32
#define L_    1024
#define D_    512
#define TOPK_ 13

// ---------------- scratch (static device globals; no allocation) ----------------
__device__ float g_q[B_*L_*D_];
__device__ float g_k[B_*L_*D_];
__device__ float g_v[B_*L_*D_];
__device__ float g_G[(size_t)B_*L_*L_];
__device__ float g_corr[B_*L_];
__device__ int   g_delay[B_*TOPK_];
__device__ float g_w[B_*TOPK_];
__device__ float g_agg[B_*L_*D_];
__device__ float g_x1[B_*L_*D_];
__device__ float g_s1[B_*L_*D_];
__device__ float g_x2[B_*L_*D_];

// ---------------- packed f32x2 helpers (Blackwell FFMA2 path) ----------------
__device__ __forceinline__ unsigned long long pack2(float x, float y) {
    unsigned long long r;
    asm("mov.b64 %0, {%1, %2};" : "=l"(r) : "f"(x), "f"(y));
    return r;
}
__device__ __forceinline__ unsigned long long dup2(float x) {
    unsigned long long r;
    asm("mov.b64 %0, {%1, %1};" : "=l"(r) : "f"(x));
    return r;
}
__device__ __forceinline__ void ffma2(unsigned long long& d,
                                      unsigned long long a,
                                      unsigned long long b) {
    asm("fma.rn.f32x2 %0, %1, %2, %0;" : "+l"(d) : "l"(a), "l"(b));
}
__device__ __forceinline__ float2 unpack2(unsigned long long v) {
    float2 r;
    asm("mov.b64 {%0, %1}, %2;" : "=f"(r.x), "=f"(r.y) : "l"(v));
    return r;
}

// ---------------- tiled SGEMM with packed-FFMA2 math + smem double buffering.
// C = A*B (+bias)(+res), optional B-transpose, batched via strides.
// BM=BN=128, BK=16, 256 threads, 8x8 per thread (acc packed along N).
template<bool TB>
__global__ __launch_bounds__(256, 2)
void sgemm_kernel(const float* __restrict__ A, const float* __restrict__ Bm,
                  const float* __restrict__ bias, const float* __restrict__ res,
                  float* __restrict__ C, int N, int K,
                  size_t sA, size_t sB, size_t sC)
{
    __shared__ float As[2][16][128];
    __shared__ float Bs[2][16][128];

    const int bz = blockIdx.z;
    A  += (size_t)bz * sA;
    Bm += (size_t)bz * sB;
    C  += (size_t)bz * sC;

    const int tid = threadIdx.x;
    const int m0  = blockIdx.y * 128;
    const int n0  = blockIdx.x * 128;

    const int tx = tid & 15;       // 16 col groups
    const int ty = tid >> 4;       // 16 row groups

    unsigned long long acc[8][4];  // 8 rows x 8 cols, packed in pairs along N
    #pragma unroll
    for (int i = 0; i < 8; i++)
        #pragma unroll
        for (int j = 0; j < 4; j++) acc[i][j] = 0ULL;

    const int arow = tid >> 2;           // 0..63
    const int acol = (tid & 3) << 2;     // 0,4,8,12
    const int brow = tid >> 5;           // 0..7
    const int bcol = (tid & 31) << 2;    // 0..124

    // ---- initial tile (k0 = 0) into buffer 0 ----
    {
        #pragma unroll
        for (int r = 0; r < 128; r += 64) {
            float4 t = *(const float4*)&A[(size_t)(m0 + arow + r)*K + acol];
            As[0][acol+0][arow+r] = t.x;
            As[0][acol+1][arow+r] = t.y;
            As[0][acol+2][arow+r] = t.z;
            As[0][acol+3][arow+r] = t.w;
        }
        if (TB) {
            #pragma unroll
            for (int r = 0; r < 128; r += 64) {
                float4 t = *(const float4*)&Bm[(size_t)(n0 + arow + r)*K + acol];
                Bs[0][acol+0][arow+r] = t.x;
                Bs[0][acol+1][arow+r] = t.y;
                Bs[0][acol+2][arow+r] = t.z;
                Bs[0][acol+3][arow+r] = t.w;
            }
        } else {
            #pragma unroll
            for (int r = 0; r < 16; r += 8) {
                *(float4*)&Bs[0][brow + r][bcol] =
                    *(const float4*)&Bm[(size_t)(brow + r)*N + n0 + bcol];
            }
        }
    }
    __syncthreads();

    int buf = 0;
    for (int k0 = 0; k0 < K; k0 += 16) {
        const bool more = (k0 + 16) < K;
        float4 pa0, pa1, pb0, pb1;
        // ---- prefetch next tile (gmem -> regs), in flight during compute ----
        if (more) {
            const int kn = k0 + 16;
            pa0 = *(const float4*)&A[(size_t)(m0 + arow     )*K + kn + acol];
            pa1 = *(const float4*)&A[(size_t)(m0 + arow + 64)*K + kn + acol];
            if (TB) {
                pb0 = *(const float4*)&Bm[(size_t)(n0 + arow     )*K + kn + acol];
                pb1 = *(const float4*)&Bm[(size_t)(n0 + arow + 64)*K + kn + acol];
            } else {
                pb0 = *(const float4*)&Bm[(size_t)(kn + brow    )*N + n0 + bcol];
                pb1 = *(const float4*)&Bm[(size_t)(kn + brow + 8)*N + n0 + bcol];
            }
        }

        // ---- compute on current buffer (packed FFMA2 math) ----
        #pragma unroll
        for (int kk = 0; kk < 16; kk++) {
            float av[8];
            *(float4*)&av[0] = *(const float4*)&As[buf][kk][ty*8];
            *(float4*)&av[4] = *(const float4*)&As[buf][kk][ty*8+4];
            const ulonglong2 bp0 = *(const ulonglong2*)&Bs[buf][kk][tx*8];
            const ulonglong2 bp1 = *(const ulonglong2*)&Bs[buf][kk][tx*8+4];
            unsigned long long b2[4] = { bp0.x, bp0.y, bp1.x, bp1.y };
            #pragma unroll
            for (int i = 0; i < 8; i++) {
                const unsigned long long a2 = dup2(av[i]);
                #pragma unroll
                for (int j = 0; j < 4; j++)
                    ffma2(acc[i][j], a2, b2[j]);
            }
        }

        // ---- store prefetched tile into the other buffer ----
        if (more) {
            const int nb = buf ^ 1;
            As[nb][acol+0][arow     ] = pa0.x;
            As[nb][acol+1][arow     ] = pa0.y;
            As[nb][acol+2][arow     ] = pa0.z;
            As[nb][acol+3][arow     ] = pa0.w;
            As[nb][acol+0][arow + 64] = pa1.x;
            As[nb][acol+1][arow + 64] = pa1.y;
            As[nb][acol+2][arow + 64] = pa1.z;
            As[nb][acol+3][arow + 64] = pa1.w;
            if (TB) {
                Bs[nb][acol+0][arow     ] = pb0.x;
                Bs[nb][acol+1][arow     ] = pb0.y;
                Bs[nb][acol+2][arow     ] = pb0.z;
                Bs[nb][acol+3][arow     ] = pb0.w;
                Bs[nb][acol+0][arow + 64] = pb1.x;
                Bs[nb][acol+1][arow + 64] = pb1.y;
                Bs[nb][acol+2][arow + 64] = pb1.z;
                Bs[nb][acol+3][arow + 64] = pb1.w;
            } else {
                *(float4*)&Bs[nb][brow    ][bcol] = pb0;
                *(float4*)&Bs[nb][brow + 8][bcol] = pb1;
            }
        }
        __syncthreads();
        buf ^= 1;
    }

    // ---- epilogue ----
    float bsv[8];
    #pragma unroll
    for (int j = 0; j < 8; j++)
        bsv[j] = bias ? bias[n0 + tx*8 + j] : 0.0f;

    #pragma unroll
    for (int i = 0; i < 8; i++) {
        const int row = m0 + ty*8 + i;
        const size_t base = (size_t)row * N + n0 + tx*8;
        #pragma unroll
        for (int jj = 0; jj < 8; jj += 4) {
            const float2 p0 = unpack2(acc[i][jj/2]);
            const float2 p1 = unpack2(acc[i][jj/2 + 1]);
            float4 o;
            o.x = p0.x + bsv[jj+0];
            o.y = p0.y + bsv[jj+1];
            o.z = p1.x + bsv[jj+2];
            o.w = p1.y + bsv[jj+3];
            if (res) {
                float4 rr = *(const float4*)&res[base + jj];
                o.x += rr.x; o.y += rr.y; o.z += rr.z; o.w += rr.w;
            }
            *(float4*)&C[base + jj] = o;
        }
    }
}

// ---------------- diagonal reduce:
// corr[b,tau] = (1/D) * sum_t G[b][(t+tau)%L][t]  ==  (1/D) * sum_r G[b][r][(r-tau)%L]
__global__ void diag_reduce_kernel(const float* __restrict__ G, float* __restrict__ corr)
{
    int gid  = blockIdx.x * blockDim.x + threadIdx.x;
    int warp = gid >> 5;
    int lane = gid & 31;
    if (warp >= B_ * L_) return;
    int b   = warp >> 10;
    int tau = warp & (L_ - 1);
    const float* Gb = G + (size_t)b * L_ * L_;
    float s = 0.0f;
    #pragma unroll 4
    for (int r = lane; r < L_; r += 32)
        s += Gb[(size_t)r * L_ + ((r - tau + L_) & (L_ - 1))];
    #pragma unroll
    for (int o = 16; o > 0; o >>= 1)
        s += __shfl_down_sync(0xffffffffu, s, o);
    if (lane == 0) corr[warp] = s * (1.0f / (float)D_);
}

// ---------------- top-13 + softmax, one block per batch
__global__ void topk_softmax_kernel(const float* __restrict__ corr,
                                    int* __restrict__ delays, float* __restrict__ w)
{
    const int b   = blockIdx.x;
    const int tid = threadIdx.x;     // 256 threads
    __shared__ float vals[L_];
    __shared__ float rv[256];
    __shared__ int   ri[256];
    __shared__ float topv[TOPK_];
    __shared__ int   topi[TOPK_];

    for (int i = tid; i < L_; i += 256) vals[i] = corr[b * L_ + i];
    __syncthreads();

    for (int sel = 0; sel < TOPK_; sel++) {
        float bv = -FLT_MAX;
        int   bi = 1 << 30;
        for (int i = tid; i < L_; i += 256) {
            float v = vals[i];
            if (v > bv || (v == bv && i < bi)) { bv = v; bi = i; }
        }
        rv[tid] = bv; ri[tid] = bi;
        __syncthreads();
        for (int s = 128; s > 0; s >>= 1) {
            if (tid < s) {
                if (rv[tid+s] > rv[tid] || (rv[tid+s] == rv[tid] && ri[tid+s] < ri[tid])) {
                    rv[tid] = rv[tid+s]; ri[tid] = ri[tid+s];
                }
            }
            __syncthreads();
        }
        if (tid == 0) {
            topv[sel] = rv[0];
            topi[sel] = ri[0];
            vals[ri[0]] = -FLT_MAX;
        }
        __syncthreads();
    }

    if (tid == 0) {
        float mx = topv[0];
        float e[TOPK_], se = 0.0f;
        #pragma unroll
        for (int i = 0; i < TOPK_; i++) { e[i] = expf(topv[i] - mx); se += e[i]; }
        float inv = 1.0f / se;
        #pragma unroll
        for (int i = 0; i < TOPK_; i++) {
            w[b*TOPK_ + i]      = e[i] * inv;
            delays[b*TOPK_ + i] = topi[i];
        }
    }
}

// ---------------- aggregation: agg[b,t,:] = sum_i w_i * V[b,(t+d_i)%L,:]
__global__ void aggregate_kernel(const float* __restrict__ V,
                                 const int* __restrict__ delays,
                                 const float* __restrict__ w,
                                 float* __restrict__ Out)
{
    const int t = blockIdx.x;
    const int b = blockIdx.y;
    const int c = threadIdx.x;   // 128 threads -> float4 over D=512
    __shared__ int   sd[TOPK_];
    __shared__ float sw[TOPK_];
    if (c < TOPK_) { sd[c] = delays[b*TOPK_ + c]; sw[c] = w[b*TOPK_ + c]; }
    __syncthreads();

    const float4* V4 = (const float4*)V;
    float4 acc = make_float4(0.f, 0.f, 0.f, 0.f);
    #pragma unroll
    for (int i = 0; i < TOPK_; i++) {
        int row = (t + sd[i]) & (L_ - 1);
        float4 vv = V4[((size_t)(b * L_ + row) * (D_/4)) + c];
        float wi = sw[i];
        acc.x = fmaf(wi, vv.x, acc.x);
        acc.y = fmaf(wi, vv.y, acc.y);
        acc.z = fmaf(wi, vv.z, acc.z);
        acc.w = fmaf(wi, vv.w, acc.w);
    }
    ((float4*)Out)[((size_t)(b * L_ + t) * (D_/4)) + c] = acc;
}

// ---------------- season = X - moving_average(X, 25) (TF SAME, count-excluding-pad)
__global__ void movavg_sub_kernel(const float* __restrict__ X, float* __restrict__ Out)
{
    const int t = blockIdx.x;
    const int b = blockIdx.y;
    const int c = threadIdx.x;   // 128 threads, float4
    const int lo = max(t - 12, 0);
    const int hi = min(t + 12, L_ - 1);
    const float4* X4 = (const float4*)X;
    float4 s = make_float4(0.f, 0.f, 0.f, 0.f);
    for (int ss = lo; ss <= hi; ss++) {
        float4 v = X4[((size_t)(b * L_ + ss) * (D_/4)) + c];
        s.x += v.x; s.y += v.y; s.z += v.z; s.w += v.w;
    }
    float inv = 1.0f / (float)(hi - lo + 1);
    float4 xv = X4[((size_t)(b * L_ + t) * (D_/4)) + c];
    float4 o;
    o.x = xv.x - s.x * inv;
    o.y = xv.y - s.y * inv;
    o.z = xv.z - s.z * inv;
    o.w = xv.w - s.w * inv;
    ((float4*)Out)[((size_t)(b * L_ + t) * (D_/4)) + c] = o;
}

// ---------------- host launch ----------------
extern "C" void kernel_launch(void* const* d_in, const int* in_sizes, int n_in,
                              void* d_out, int out_size)
{
    const float* x  = (const float*)d_in[0];
    const float* Wq = (const float*)d_in[1];
    const float* bq = (const float*)d_in[2];
    const float* Wk = (const float*)d_in[3];
    const float* bk = (const float*)d_in[4];
    const float* Wv = (const float*)d_in[5];
    const float* bv = (const float*)d_in[6];
    const float* Wo = (const float*)d_in[7];
    const float* bo = (const float*)d_in[8];
    const float* Wd = (const float*)d_in[9];
    const float* bd = (const float*)d_in[10];
    float* out = (float*)d_out;

    float *q, *k, *v, *G, *corr, *w, *agg, *x1, *s1, *x2;
    int* dl;
    cudaGetSymbolAddress((void**)&q,    g_q);
    cudaGetSymbolAddress((void**)&k,    g_k);
    cudaGetSymbolAddress((void**)&v,    g_v);
    cudaGetSymbolAddress((void**)&G,    g_G);
    cudaGetSymbolAddress((void**)&corr, g_corr);
    cudaGetSymbolAddress((void**)&dl,   g_delay);
    cudaGetSymbolAddress((void**)&w,    g_w);
    cudaGetSymbolAddress((void**)&agg,  g_agg);
    cudaGetSymbolAddress((void**)&x1,   g_x1);
    cudaGetSymbolAddress((void**)&s1,   g_s1);
    cudaGetSymbolAddress((void**)&x2,   g_x2);

    dim3 t256(256);
    dim3 gproj(D_/128, (B_*L_)/128, 1);      // (4, 256)
    dim3 ggram(L_/128, L_/128, B_);          // (8, 8, 32)
    dim3 gld(L_, B_);

    // Q/K/V projections
    sgemm_kernel<false><<<gproj, t256>>>(x, Wq, bq, nullptr, q, D_, D_, 0, 0, 0);
    sgemm_kernel<false><<<gproj, t256>>>(x, Wk, bk, nullptr, k, D_, D_, 0, 0, 0);
    sgemm_kernel<false><<<gproj, t256>>>(x, Wv, bv, nullptr, v, D_, D_, 0, 0, 0);

    // batched Gram: G[b] = Q[b] @ K[b]^T
    sgemm_kernel<true><<<ggram, t256>>>(q, k, nullptr, nullptr, G, L_, D_,
                                        (size_t)L_*D_, (size_t)L_*D_, (size_t)L_*L_);

    // circular-diagonal reduction -> mean_corr
    {
        int warps = B_ * L_;
        int threads = 256;
        int blocks = (warps * 32 + threads - 1) / threads;
        diag_reduce_kernel<<<blocks, threads>>>(G, corr);
    }

    // top-13 + softmax per batch
    topk_softmax_kernel<<<B_, 256>>>(corr, dl, w);

    // delay aggregation of V
    aggregate_kernel<<<gld, 128>>>(v, dl, w, agg);

    // ac = agg @ Wo + bo; x1 = ac + x  (residual fused)
    sgemm_kernel<false><<<gproj, t256>>>(agg, Wo, bo, x, x1, D_, D_, 0, 0, 0);

    // series decomp 1: s1 = x1 - movavg(x1)
    movavg_sub_kernel<<<gld, 128>>>(x1, s1);

    // x2 = s1 @ Wd + bd + s1 (residual fused)
    sgemm_kernel<false><<<gproj, t256>>>(s1, Wd, bd, s1, x2, D_, D_, 0, 0, 0);

    // series decomp 2 -> output
    movavg_sub_kernel<<<gld, 128>>>(x2, out);
}

// round 6
// speedup vs baseline: 1.6127x; 1.6014x over previous
#include <cuda_runtime.h>
#include <cuda_bf16.h>
#include <math.h>
#include <float.h>
#include <stdint.h>

#define B_    32
#define L_    1024
#define D_    512
#define TOPK_ 13

// ---------------- scratch (static device globals; no allocation) ----------------
__device__ float g_q[B_*L_*D_];
__device__ float g_k[B_*L_*D_];
__device__ float g_v[B_*L_*D_];
__device__ float g_G[(size_t)B_*L_*L_];
__device__ float g_corr[B_*L_];
__device__ int   g_delay[B_*TOPK_];
__device__ float g_w[B_*TOPK_];
__device__ float g_agg[B_*L_*D_];
__device__ float g_x1[B_*L_*D_];
__device__ float g_s1[B_*L_*D_];
__device__ float g_x2[B_*L_*D_];
__device__ float g_wt[5*D_*D_];   // transposed weights: Wq,Wk,Wv,Wo,Wd

// ================= portable PTX helpers (sm_80+; no arch-'a' features) =========
__device__ __forceinline__ uint32_t smem_to_u32(const void* p) {
    uint32_t a;
    asm("{ .reg .u64 t; cvta.to.shared.u64 t, %1; cvt.u32.u64 %0, t; }" : "=r"(a) : "l"(p));
    return a;
}
#define LDMX4(r0,r1,r2,r3,addr) \
    asm volatile("ldmatrix.sync.aligned.m8n8.x4.shared.b16 {%0,%1,%2,%3}, [%4];" \
        : "=r"(r0), "=r"(r1), "=r"(r2), "=r"(r3) : "r"(addr))
#define LDMX2(r0,r1,addr) \
    asm volatile("ldmatrix.sync.aligned.m8n8.x2.shared.b16 {%0,%1}, [%2];" \
        : "=r"(r0), "=r"(r1) : "r"(addr))
#define MMA16816(c,a,b) \
    asm volatile("mma.sync.aligned.m16n8k16.row.col.f32.bf16.bf16.f32 " \
        "{%0,%1,%2,%3},{%4,%5,%6,%7},{%8,%9},{%0,%1,%2,%3};" \
        : "+f"((c)[0]), "+f"((c)[1]), "+f"((c)[2]), "+f"((c)[3]) \
        : "r"((a)[0]), "r"((a)[1]), "r"((a)[2]), "r"((a)[3]), "r"((b)[0]), "r"((b)[1]))

// ================= bf16x2-split MMA GEMM: C = A * Bm^T (+bias)(+res) ==========
// A: [M,512] fp32 row-major; Bm: [Nrows,512] fp32 row-major ("NT", k contiguous).
// CTA tile 128x128, BK=32, 8 warps (warp tile 32m x 64n), 3-product bf16 split.
// smem per stage: A_hi[128][32] / A_mid / B_hi / B_mid, rows padded to 80B.
#define ROWB   80            // bytes per smem row (32 bf16 = 64B + 16B pad)
#define TILEB  (128*ROWB)    // 10240
#define STAGEB (4*TILEB)     // 40960
#define SMEM_MMA (2*STAGEB)  // 81920

__device__ __forceinline__ void split_store(float4 v, char* hi, char* mid) {
    __nv_bfloat162 h0 = __float22bfloat162_rn(make_float2(v.x, v.y));
    __nv_bfloat162 h1 = __float22bfloat162_rn(make_float2(v.z, v.w));
    float2 r0 = make_float2(v.x - __bfloat162float(h0.x), v.y - __bfloat162float(h0.y));
    float2 r1 = make_float2(v.z - __bfloat162float(h1.x), v.w - __bfloat162float(h1.y));
    __nv_bfloat162 m0 = __float22bfloat162_rn(r0);
    __nv_bfloat162 m1 = __float22bfloat162_rn(r1);
    uint2 hv, mv;
    hv.x = *(uint32_t*)&h0; hv.y = *(uint32_t*)&h1;
    mv.x = *(uint32_t*)&m0; mv.y = *(uint32_t*)&m1;
    *(uint2*)hi  = hv;
    *(uint2*)mid = mv;
}

__global__ __launch_bounds__(256, 2)
void gemm_mma(const float* __restrict__ A, const float* __restrict__ Bm,
              const float* __restrict__ bias, const float* __restrict__ res,
              float* __restrict__ C, int N, size_t sA, size_t sB, size_t sC)
{
    extern __shared__ __align__(128) char smem[];
    const int tid  = threadIdx.x;
    const int wid  = tid >> 5;
    const int lane = tid & 31;
    const int bz   = blockIdx.z;
    A  += (size_t)bz * sA;
    Bm += (size_t)bz * sB;
    C  += (size_t)bz * sC;
    const int m0 = blockIdx.y * 128;
    const int n0 = blockIdx.x * 128;
    const uint32_t sb = smem_to_u32(smem);

    const int g  = lane >> 2, tg = lane & 3;
    const int wm = wid >> 1,  wn = wid & 1;     // warp tile: rows wm*32, cols wn*64

    // gmem load mapping: each thread loads 4 float4 of A and 4 of B per chunk
    const int lrow = tid >> 1;          // 0..127
    const int lk   = (tid & 1) * 16;    // 0 or 16

    float acc[2][8][4];
    #pragma unroll
    for (int i = 0; i < 2; i++)
        #pragma unroll
        for (int j = 0; j < 8; j++)
            #pragma unroll
            for (int r = 0; r < 4; r++) acc[i][j][r] = 0.0f;

    // ldmatrix per-lane address components
    const int asel = lane >> 3, ar = lane & 7;          // x4: 4 mats
    const int arowq = (asel & 1) * 8 + ar;              // row within 16
    const int akq   = (asel >> 1) * 8;                  // k offset within 16
    const int br = lane & 7, bsel = (lane >> 3) & 1;    // x2: 2 mats (lanes 0-15)

    float4 pa[4], pb[4];
    // ---- chunk 0 load + convert ----
    #pragma unroll
    for (int i = 0; i < 4; i++) {
        pa[i] = *(const float4*)&A [(size_t)(m0 + lrow)*D_ + lk + i*4];
        pb[i] = *(const float4*)&Bm[(size_t)(n0 + lrow)*D_ + lk + i*4];
    }
    {
        char* st = smem;
        const int off = lrow*ROWB + lk*2;
        #pragma unroll
        for (int i = 0; i < 4; i++) {
            split_store(pa[i], st + off + i*8,           st + TILEB   + off + i*8);
            split_store(pb[i], st + 2*TILEB + off + i*8, st + 3*TILEB + off + i*8);
        }
    }
    __syncthreads();

    for (int c = 0; c < 16; ++c) {
        const int s = c & 1;
        // prefetch next chunk (gmem -> regs), overlapped with MMA below
        if (c < 15) {
            const int k0 = (c + 1) * 32;
            #pragma unroll
            for (int i = 0; i < 4; i++) {
                pa[i] = *(const float4*)&A [(size_t)(m0 + lrow)*D_ + k0 + lk + i*4];
                pb[i] = *(const float4*)&Bm[(size_t)(n0 + lrow)*D_ + k0 + lk + i*4];
            }
        }

        // ---- compute on stage s ----
        const uint32_t aHi  = sb + s*STAGEB;
        const uint32_t aMid = aHi + TILEB;
        const uint32_t bHi  = aHi + 2*TILEB;
        const uint32_t bMid = aHi + 3*TILEB;

        #pragma unroll
        for (int kk = 0; kk < 32; kk += 16) {
            uint32_t ah[2][4], am[2][4];
            #pragma unroll
            for (int mt = 0; mt < 2; mt++) {
                const uint32_t ao = (uint32_t)((wm*32 + mt*16 + arowq)*ROWB + (kk + akq)*2);
                LDMX4(ah[mt][0], ah[mt][1], ah[mt][2], ah[mt][3], aHi  + ao);
                LDMX4(am[mt][0], am[mt][1], am[mt][2], am[mt][3], aMid + ao);
            }
            #pragma unroll
            for (int nt = 0; nt < 8; nt++) {
                const uint32_t bo = (uint32_t)((wn*64 + nt*8 + br)*ROWB + (kk + bsel*8)*2);
                uint32_t bh[2], bm2[2];
                LDMX2(bh[0],  bh[1],  bHi  + bo);
                LDMX2(bm2[0], bm2[1], bMid + bo);
                #pragma unroll
                for (int mt = 0; mt < 2; mt++) {
                    MMA16816(acc[mt][nt], ah[mt], bh);
                    MMA16816(acc[mt][nt], ah[mt], bm2);
                    MMA16816(acc[mt][nt], am[mt], bh);
                }
            }
        }
        __syncthreads();

        // ---- store prefetched chunk into the other stage ----
        if (c < 15) {
            char* st = smem + (s ^ 1)*STAGEB;
            const int off = lrow*ROWB + lk*2;
            #pragma unroll
            for (int i = 0; i < 4; i++) {
                split_store(pa[i], st + off + i*8,           st + TILEB   + off + i*8);
                split_store(pb[i], st + 2*TILEB + off + i*8, st + 3*TILEB + off + i*8);
            }
            __syncthreads();
        }
    }

    // ---- epilogue: fp32 accumulators -> gmem with fused bias/residual ----
    #pragma unroll
    for (int mt = 0; mt < 2; mt++) {
        const int row0 = m0 + wm*32 + mt*16 + g;
        #pragma unroll
        for (int nt = 0; nt < 8; nt++) {
            const int col = n0 + wn*64 + nt*8 + tg*2;
            float b0 = 0.f, b1 = 0.f;
            if (bias) { b0 = bias[col]; b1 = bias[col + 1]; }
            float2 v0 = make_float2(acc[mt][nt][0] + b0, acc[mt][nt][1] + b1);
            float2 v1 = make_float2(acc[mt][nt][2] + b0, acc[mt][nt][3] + b1);
            const size_t i0 = (size_t)row0 * N + col;
            const size_t i1 = (size_t)(row0 + 8) * N + col;
            if (res) {
                float2 r0 = *(const float2*)&res[i0];
                float2 r1 = *(const float2*)&res[i1];
                v0.x += r0.x; v0.y += r0.y;
                v1.x += r1.x; v1.y += r1.y;
            }
            *(float2*)&C[i0] = v0;
            *(float2*)&C[i1] = v1;
        }
    }
}

// ---------------- 512x512 transpose: out[n][k] = in[k][n] ----------------
__global__ void transpose512_kernel(const float* __restrict__ in, float* __restrict__ out)
{
    __shared__ float t[32][33];
    const int bx = blockIdx.x * 32, by = blockIdx.y * 32;
    const int tx = threadIdx.x, ty = threadIdx.y;   // 32 x 8
    #pragma unroll
    for (int r = 0; r < 32; r += 8)
        t[ty + r][tx] = in[(size_t)(by + ty + r) * D_ + bx + tx];
    __syncthreads();
    #pragma unroll
    for (int r = 0; r < 32; r += 8)
        out[(size_t)(bx + ty + r) * D_ + by + tx] = t[tx][ty + r];
}

// ---------------- diagonal reduce:
// corr[b,tau] = (1/D) * sum_r G[b][r][(r-tau)%L]
__global__ void diag_reduce_kernel(const float* __restrict__ G, float* __restrict__ corr)
{
    int gid  = blockIdx.x * blockDim.x + threadIdx.x;
    int warp = gid >> 5;
    int lane = gid & 31;
    if (warp >= B_ * L_) return;
    int b   = warp >> 10;
    int tau = warp & (L_ - 1);
    const float* Gb = G + (size_t)b * L_ * L_;
    float s = 0.0f;
    #pragma unroll 4
    for (int r = lane; r < L_; r += 32)
        s += Gb[(size_t)r * L_ + ((r - tau + L_) & (L_ - 1))];
    #pragma unroll
    for (int o = 16; o > 0; o >>= 1)
        s += __shfl_down_sync(0xffffffffu, s, o);
    if (lane == 0) corr[warp] = s * (1.0f / (float)D_);
}

// ---------------- top-13 + softmax, one block per batch
__global__ void topk_softmax_kernel(const float* __restrict__ corr,
                                    int* __restrict__ delays, float* __restrict__ w)
{
    const int b   = blockIdx.x;
    const int tid = threadIdx.x;     // 256 threads
    __shared__ float vals[L_];
    __shared__ float rv[256];
    __shared__ int   ri[256];
    __shared__ float topv[TOPK_];
    __shared__ int   topi[TOPK_];

    for (int i = tid; i < L_; i += 256) vals[i] = corr[b * L_ + i];
    __syncthreads();

    for (int sel = 0; sel < TOPK_; sel++) {
        float bv = -FLT_MAX;
        int   bi = 1 << 30;
        for (int i = tid; i < L_; i += 256) {
            float v = vals[i];
            if (v > bv || (v == bv && i < bi)) { bv = v; bi = i; }
        }
        rv[tid] = bv; ri[tid] = bi;
        __syncthreads();
        for (int s = 128; s > 0; s >>= 1) {
            if (tid < s) {
                if (rv[tid+s] > rv[tid] || (rv[tid+s] == rv[tid] && ri[tid+s] < ri[tid])) {
                    rv[tid] = rv[tid+s]; ri[tid] = ri[tid+s];
                }
            }
            __syncthreads();
        }
        if (tid == 0) {
            topv[sel] = rv[0];
            topi[sel] = ri[0];
            vals[ri[0]] = -FLT_MAX;
        }
        __syncthreads();
    }

    if (tid == 0) {
        float mx = topv[0];
        float e[TOPK_], se = 0.0f;
        #pragma unroll
        for (int i = 0; i < TOPK_; i++) { e[i] = expf(topv[i] - mx); se += e[i]; }
        float inv = 1.0f / se;
        #pragma unroll
        for (int i = 0; i < TOPK_; i++) {
            w[b*TOPK_ + i]      = e[i] * inv;
            delays[b*TOPK_ + i] = topi[i];
        }
    }
}

// ---------------- aggregation: agg[b,t,:] = sum_i w_i * V[b,(t+d_i)%L,:]
__global__ void aggregate_kernel(const float* __restrict__ V,
                                 const int* __restrict__ delays,
                                 const float* __restrict__ w,
                                 float* __restrict__ Out)
{
    const int t = blockIdx.x;
    const int b = blockIdx.y;
    const int c = threadIdx.x;   // 128 threads -> float4 over D=512
    __shared__ int   sd[TOPK_];
    __shared__ float sw[TOPK_];
    if (c < TOPK_) { sd[c] = delays[b*TOPK_ + c]; sw[c] = w[b*TOPK_ + c]; }
    __syncthreads();

    const float4* V4 = (const float4*)V;
    float4 acc = make_float4(0.f, 0.f, 0.f, 0.f);
    #pragma unroll
    for (int i = 0; i < TOPK_; i++) {
        int row = (t + sd[i]) & (L_ - 1);
        float4 vv = V4[((size_t)(b * L_ + row) * (D_/4)) + c];
        float wi = sw[i];
        acc.x = fmaf(wi, vv.x, acc.x);
        acc.y = fmaf(wi, vv.y, acc.y);
        acc.z = fmaf(wi, vv.z, acc.z);
        acc.w = fmaf(wi, vv.w, acc.w);
    }
    ((float4*)Out)[((size_t)(b * L_ + t) * (D_/4)) + c] = acc;
}

// ---------------- season = X - moving_average(X, 25) (TF SAME, count-excluding-pad)
__global__ void movavg_sub_kernel(const float* __restrict__ X, float* __restrict__ Out)
{
    const int t = blockIdx.x;
    const int b = blockIdx.y;
    const int c = threadIdx.x;   // 128 threads, float4
    const int lo = max(t - 12, 0);
    const int hi = min(t + 12, L_ - 1);
    const float4* X4 = (const float4*)X;
    float4 s = make_float4(0.f, 0.f, 0.f, 0.f);
    for (int ss = lo; ss <= hi; ss++) {
        float4 v = X4[((size_t)(b * L_ + ss) * (D_/4)) + c];
        s.x += v.x; s.y += v.y; s.z += v.z; s.w += v.w;
    }
    float inv = 1.0f / (float)(hi - lo + 1);
    float4 xv = X4[((size_t)(b * L_ + t) * (D_/4)) + c];
    float4 o;
    o.x = xv.x - s.x * inv;
    o.y = xv.y - s.y * inv;
    o.z = xv.z - s.z * inv;
    o.w = xv.w - s.w * inv;
    ((float4*)Out)[((size_t)(b * L_ + t) * (D_/4)) + c] = o;
}

// ---------------- host launch ----------------
extern "C" void kernel_launch(void* const* d_in, const int* in_sizes, int n_in,
                              void* d_out, int out_size)
{
    const float* x  = (const float*)d_in[0];
    const float* Wq = (const float*)d_in[1];
    const float* bq = (const float*)d_in[2];
    const float* Wk = (const float*)d_in[3];
    const float* bk = (const float*)d_in[4];
    const float* Wv = (const float*)d_in[5];
    const float* bv = (const float*)d_in[6];
    const float* Wo = (const float*)d_in[7];
    const float* bo = (const float*)d_in[8];
    const float* Wd = (const float*)d_in[9];
    const float* bd = (const float*)d_in[10];
    float* out = (float*)d_out;

    float *q, *k, *v, *G, *corr, *w, *agg, *x1, *s1, *x2, *wt;
    int* dl;
    cudaGetSymbolAddress((void**)&q,    g_q);
    cudaGetSymbolAddress((void**)&k,    g_k);
    cudaGetSymbolAddress((void**)&v,    g_v);
    cudaGetSymbolAddress((void**)&G,    g_G);
    cudaGetSymbolAddress((void**)&corr, g_corr);
    cudaGetSymbolAddress((void**)&dl,   g_delay);
    cudaGetSymbolAddress((void**)&w,    g_w);
    cudaGetSymbolAddress((void**)&agg,  g_agg);
    cudaGetSymbolAddress((void**)&x1,   g_x1);
    cudaGetSymbolAddress((void**)&s1,   g_s1);
    cudaGetSymbolAddress((void**)&x2,   g_x2);
    cudaGetSymbolAddress((void**)&wt,   g_wt);

    cudaFuncSetAttribute(gemm_mma, cudaFuncAttributeMaxDynamicSharedMemorySize, SMEM_MMA);

    float* wtq = wt + 0*D_*D_;
    float* wtk = wt + 1*D_*D_;
    float* wtv = wt + 2*D_*D_;
    float* wto = wt + 3*D_*D_;
    float* wtd = wt + 4*D_*D_;

    dim3 tT(32, 8), gT(16, 16);
    transpose512_kernel<<<gT, tT>>>(Wq, wtq);
    transpose512_kernel<<<gT, tT>>>(Wk, wtk);
    transpose512_kernel<<<gT, tT>>>(Wv, wtv);
    transpose512_kernel<<<gT, tT>>>(Wo, wto);
    transpose512_kernel<<<gT, tT>>>(Wd, wtd);

    dim3 t256(256);
    dim3 gdense(D_/128, (B_*L_)/128, 1);     // (4, 256, 1)
    dim3 ggram(L_/128, L_/128, B_);          // (8, 8, 32)
    dim3 gld(L_, B_);

    // Q/K/V projections: C = x @ Wt^T (+b)
    gemm_mma<<<gdense, t256, SMEM_MMA>>>(x, wtq, bq, nullptr, q, D_, 0, 0, 0);
    gemm_mma<<<gdense, t256, SMEM_MMA>>>(x, wtk, bk, nullptr, k, D_, 0, 0, 0);
    gemm_mma<<<gdense, t256, SMEM_MMA>>>(x, wtv, bv, nullptr, v, D_, 0, 0, 0);

    // batched Gram: G[b] = Q[b] @ K[b]^T
    gemm_mma<<<ggram, t256, SMEM_MMA>>>(q, k, nullptr, nullptr, G, L_,
                                        (size_t)L_*D_, (size_t)L_*D_, (size_t)L_*L_);

    // circular-diagonal reduction -> mean_corr
    {
        int warps = B_ * L_;
        int threads = 256;
        int blocks = (warps * 32 + threads - 1) / threads;
        diag_reduce_kernel<<<blocks, threads>>>(G, corr);
    }

    // top-13 + softmax per batch
    topk_softmax_kernel<<<B_, 256>>>(corr, dl, w);

    // delay aggregation of V
    aggregate_kernel<<<gld, 128>>>(v, dl, w, agg);

    // ac = agg @ Wo + bo; x1 = ac + x  (residual fused)
    gemm_mma<<<gdense, t256, SMEM_MMA>>>(agg, wto, bo, x, x1, D_, 0, 0, 0);

    // series decomp 1: s1 = x1 - movavg(x1)
    movavg_sub_kernel<<<gld, 128>>>(x1, s1);

    // x2 = s1 @ Wd + bd + s1 (residual fused)
    gemm_mma<<<gdense, t256, SMEM_MMA>>>(s1, wtd, bd, s1, x2, D_, 0, 0, 0);

    // series decomp 2 -> output
    movavg_sub_kernel<<<gld, 128>>>(x2, out);
}

// round 7
// speedup vs baseline: 1.9494x; 1.2088x over previous
#include <cuda_runtime.h>
#include <cuda_bf16.h>
#include <math.h>
#include <float.h>
#include <stdint.h>

#define B_    32
#define L_    1024
#define D_    512
#define TOPK_ 13
#define NEL_  (B_*L_*D_)

// ---------------- scratch (static device globals; no allocation) ----------------
__device__ float g_v [NEL_];
__device__ float g_x1[NEL_];
__device__ float g_s1[NEL_];
__device__ float g_x2[NEL_];
__device__ float g_corr[B_*L_];
__device__ int   g_delay[B_*TOPK_];
__device__ float g_w[B_*TOPK_];
__device__ __nv_bfloat16 g_xh[NEL_],  g_xm[NEL_];
__device__ __nv_bfloat16 g_qh[NEL_],  g_qm[NEL_];
__device__ __nv_bfloat16 g_kh[NEL_],  g_km[NEL_];
__device__ __nv_bfloat16 g_ah[NEL_],  g_am[NEL_];
__device__ __nv_bfloat16 g_sh[NEL_],  g_sm[NEL_];
__device__ __nv_bfloat16 g_wth[5*D_*D_], g_wtm[5*D_*D_];

// ================= portable PTX helpers (sm_80+; no arch-'a' features) =========
__device__ __forceinline__ uint32_t smem_to_u32(const void* p) {
    uint32_t a;
    asm("{ .reg .u64 t; cvta.to.shared.u64 t, %1; cvt.u32.u64 %0, t; }" : "=r"(a) : "l"(p));
    return a;
}
#define LDMX4(r0,r1,r2,r3,addr) \
    asm volatile("ldmatrix.sync.aligned.m8n8.x4.shared.b16 {%0,%1,%2,%3}, [%4];" \
        : "=r"(r0), "=r"(r1), "=r"(r2), "=r"(r3) : "r"(addr))
#define LDMX2(r0,r1,addr) \
    asm volatile("ldmatrix.sync.aligned.m8n8.x2.shared.b16 {%0,%1}, [%2];" \
        : "=r"(r0), "=r"(r1) : "r"(addr))
#define MMA16816(c,a,b) \
    asm volatile("mma.sync.aligned.m16n8k16.row.col.f32.bf16.bf16.f32 " \
        "{%0,%1,%2,%3},{%4,%5,%6,%7},{%8,%9},{%0,%1,%2,%3};" \
        : "+f"((c)[0]), "+f"((c)[1]), "+f"((c)[2]), "+f"((c)[3]) \
        : "r"((a)[0]), "r"((a)[1]), "r"((a)[2]), "r"((a)[3]), "r"((b)[0]), "r"((b)[1]))
#define CP16(dst, src) \
    asm volatile("cp.async.cg.shared.global [%0], [%1], 16;" :: "r"(dst), "l"(src) : "memory")
#define CPCOMMIT() asm volatile("cp.async.commit_group;" ::: "memory")
#define CPWAIT1()  asm volatile("cp.async.wait_group 1;" ::: "memory")
#define CPWAIT0()  asm volatile("cp.async.wait_group 0;" ::: "memory")

// split fp32 pair -> bf16 hi + bf16 mid, store as bf16x2
__device__ __forceinline__ void split2_store(float2 v, __nv_bfloat16* H, __nv_bfloat16* M, size_t e) {
    __nv_bfloat162 h = __float22bfloat162_rn(v);
    float2 r = make_float2(v.x - __bfloat162float(h.x), v.y - __bfloat162float(h.y));
    __nv_bfloat162 m = __float22bfloat162_rn(r);
    *(__nv_bfloat162*)(H + e) = h;
    *(__nv_bfloat162*)(M + e) = m;
}

// ================= bf16 split-operand MMA GEMM ===============================
// A(h/m): [Mrows,512] bf16 NT; B(h/m): [Nrows,512] bf16 NT. K=512 fixed.
// CTA 128x128, BK=32, 8 warps (warp tile 32m x 64n), 3-product accumulate.
// smem stage = 4 tiles (Ah, Am, Bh, Bm); tile = 128 rows x 32 bf16, row stride 80B.
#define ROWB   80
#define TILEB  (128*ROWB)      // 10240
#define STAGEB (4*TILEB)       // 40960
#define SMEM_MMA (2*STAGEB)    // 81920

__global__ __launch_bounds__(256, 2)
void gemm_bf(const __nv_bfloat16* __restrict__ Ah, const __nv_bfloat16* __restrict__ Am,
             const __nv_bfloat16* __restrict__ Bh, const __nv_bfloat16* __restrict__ Bm,
             const float* __restrict__ bias, const float* __restrict__ res,
             float* __restrict__ outF, __nv_bfloat16* __restrict__ outH,
             __nv_bfloat16* __restrict__ outM, float* __restrict__ corr,
             size_t sAB, int gram)
{
    extern __shared__ __align__(128) char smem[];
    const int tid  = threadIdx.x;
    const int wid  = tid >> 5;
    const int lane = tid & 31;
    const int bz   = blockIdx.z;
    Ah += (size_t)bz * sAB;  Am += (size_t)bz * sAB;
    Bh += (size_t)bz * sAB;  Bm += (size_t)bz * sAB;
    const int m0 = blockIdx.y * 128;
    const int n0 = blockIdx.x * 128;
    const uint32_t sb = smem_to_u32(smem);

    const int g  = lane >> 2, tg = lane & 3;
    const int wm = wid >> 1,  wn = wid & 1;

    float acc[2][8][4];
    #pragma unroll
    for (int i = 0; i < 2; i++)
        #pragma unroll
        for (int j = 0; j < 8; j++)
            #pragma unroll
            for (int r = 0; r < 4; r++) acc[i][j][r] = 0.0f;

    // ldmatrix per-lane address components (validated in R6)
    const int asel = lane >> 3, ar = lane & 7;
    const int arowq = (asel & 1) * 8 + ar;
    const int akq   = (asel >> 1) * 8;
    const int br = lane & 7, bsel = (lane >> 3) & 1;

    // cp.async mapping: thread -> (row = tid>>1, two 16B chunks)
    const int crow = tid >> 1;
    const int coff = (tid & 1);            // 0 or 1 -> elems 0/16
    const __nv_bfloat16* Ahp = Ah + (size_t)(m0 + crow) * D_ + coff * 16;
    const __nv_bfloat16* Amp = Am + (size_t)(m0 + crow) * D_ + coff * 16;
    const __nv_bfloat16* Bhp = Bh + (size_t)(n0 + crow) * D_ + coff * 16;
    const __nv_bfloat16* Bmp = Bm + (size_t)(n0 + crow) * D_ + coff * 16;
    const uint32_t drow = (uint32_t)(crow * ROWB + coff * 32);

    auto issue = [&](int c, int s) {
        const uint32_t db = sb + s * STAGEB + drow;
        const size_t go = (size_t)c * 32;
        CP16(db + 0*TILEB,      Ahp + go);
        CP16(db + 0*TILEB + 16, Ahp + go + 8);
        CP16(db + 1*TILEB,      Amp + go);
        CP16(db + 1*TILEB + 16, Amp + go + 8);
        CP16(db + 2*TILEB,      Bhp + go);
        CP16(db + 2*TILEB + 16, Bhp + go + 8);
        CP16(db + 3*TILEB,      Bmp + go);
        CP16(db + 3*TILEB + 16, Bmp + go + 8);
    };

    issue(0, 0); CPCOMMIT();

    for (int c = 0; c < 16; ++c) {
        const int s = c & 1;
        if (c < 15) { issue(c + 1, s ^ 1); CPCOMMIT(); CPWAIT1(); }
        else        { CPWAIT0(); }
        __syncthreads();

        const uint32_t aHi  = sb + s*STAGEB;
        const uint32_t aMid = aHi + TILEB;
        const uint32_t bHi  = aHi + 2*TILEB;
        const uint32_t bMid = aHi + 3*TILEB;

        #pragma unroll
        for (int kk = 0; kk < 32; kk += 16) {
            uint32_t ah[2][4], am[2][4], bh[8][2];
            #pragma unroll
            for (int mt = 0; mt < 2; mt++) {
                const uint32_t ao = (uint32_t)((wm*32 + mt*16 + arowq)*ROWB + (kk + akq)*2);
                LDMX4(ah[mt][0], ah[mt][1], ah[mt][2], ah[mt][3], aHi  + ao);
                LDMX4(am[mt][0], am[mt][1], am[mt][2], am[mt][3], aMid + ao);
            }
            #pragma unroll
            for (int nt = 0; nt < 8; nt++) {
                const uint32_t bo = (uint32_t)((wn*64 + nt*8 + br)*ROWB + (kk + bsel*8)*2);
                LDMX2(bh[nt][0], bh[nt][1], bHi + bo);
            }
            // pass 1: hi*hi (acc reuse distance 16)
            #pragma unroll
            for (int nt = 0; nt < 8; nt++)
                #pragma unroll
                for (int mt = 0; mt < 2; mt++)
                    MMA16816(acc[mt][nt], ah[mt], bh[nt]);
            // pass 2: mid_A * hi_B
            #pragma unroll
            for (int nt = 0; nt < 8; nt++)
                #pragma unroll
                for (int mt = 0; mt < 2; mt++)
                    MMA16816(acc[mt][nt], am[mt], bh[nt]);
            // pass 3: hi_A * mid_B in nt-groups of 4 (distance 8)
            #pragma unroll
            for (int ng = 0; ng < 2; ng++) {
                uint32_t bm2[4][2];
                #pragma unroll
                for (int j = 0; j < 4; j++) {
                    const int nt = ng*4 + j;
                    const uint32_t bo = (uint32_t)((wn*64 + nt*8 + br)*ROWB + (kk + bsel*8)*2);
                    LDMX2(bm2[j][0], bm2[j][1], bMid + bo);
                }
                #pragma unroll
                for (int j = 0; j < 4; j++)
                    #pragma unroll
                    for (int mt = 0; mt < 2; mt++)
                        MMA16816(acc[mt][ng*4 + j], ah[mt], bm2[j]);
            }
        }
        __syncthreads();
    }

    if (gram) {
        // fused circular-diagonal reduction: element (r,c) -> tau = (r - c) mod L
        float* buf = (float*)smem;
        for (int i = tid; i < 255; i += 256) buf[i] = 0.0f;
        __syncthreads();
        #pragma unroll
        for (int mt = 0; mt < 2; mt++) {
            const int lr0 = wm*32 + mt*16 + g;
            #pragma unroll
            for (int nt = 0; nt < 8; nt++) {
                const int lc0 = wn*64 + nt*8 + tg*2;
                atomicAdd(&buf[lr0     - lc0     + 127], acc[mt][nt][0]);
                atomicAdd(&buf[lr0     - lc0 - 1 + 127], acc[mt][nt][1]);
                atomicAdd(&buf[lr0 + 8 - lc0     + 127], acc[mt][nt][2]);
                atomicAdd(&buf[lr0 + 8 - lc0 - 1 + 127], acc[mt][nt][3]);
            }
        }
        __syncthreads();
        float* cb = corr + (size_t)bz * L_;
        for (int i = tid; i < 255; i += 256) {
            const int tau = (m0 - n0 + i - 127) & (L_ - 1);
            atomicAdd(&cb[tau], buf[i] * (1.0f / (float)D_));
        }
        return;
    }

    // ---- epilogue: bias/res fused; fp32 out and/or bf16 hi/mid split out ----
    #pragma unroll
    for (int mt = 0; mt < 2; mt++) {
        const int row0 = m0 + wm*32 + mt*16 + g;
        #pragma unroll
        for (int nt = 0; nt < 8; nt++) {
            const int col = n0 + wn*64 + nt*8 + tg*2;
            float b0 = 0.f, b1 = 0.f;
            if (bias) { b0 = bias[col]; b1 = bias[col + 1]; }
            float2 v0 = make_float2(acc[mt][nt][0] + b0, acc[mt][nt][1] + b1);
            float2 v1 = make_float2(acc[mt][nt][2] + b0, acc[mt][nt][3] + b1);
            const size_t i0 = (size_t)row0 * D_ + col;
            const size_t i1 = (size_t)(row0 + 8) * D_ + col;
            if (res) {
                float2 r0 = *(const float2*)&res[i0];
                float2 r1 = *(const float2*)&res[i1];
                v0.x += r0.x; v0.y += r0.y;
                v1.x += r1.x; v1.y += r1.y;
            }
            if (outF) {
                *(float2*)&outF[i0] = v0;
                *(float2*)&outF[i1] = v1;
            }
            if (outH) {
                split2_store(v0, outH, outM, i0);
                split2_store(v1, outH, outM, i1);
            }
        }
    }
}

// ---------------- x -> hi/mid bf16 split ----------------
__global__ void xsplit_kernel(const float* __restrict__ X,
                              __nv_bfloat16* __restrict__ H, __nv_bfloat16* __restrict__ M)
{
    const size_t i = (size_t)blockIdx.x * blockDim.x + threadIdx.x;   // float4 idx
    float4 v = ((const float4*)X)[i];
    split2_store(make_float2(v.x, v.y), H, M, i*4);
    split2_store(make_float2(v.z, v.w), H, M, i*4 + 2);
}

// ---------------- weight transpose + split: out[n][k] = split(in[k][n]) -------
__global__ void wtsplit_kernel(const float* __restrict__ in,
                               __nv_bfloat16* __restrict__ oh, __nv_bfloat16* __restrict__ om)
{
    __shared__ float t[32][33];
    const int bx = blockIdx.x * 32, by = blockIdx.y * 32;
    const int tx = threadIdx.x, ty = threadIdx.y;   // 32 x 8
    #pragma unroll
    for (int r = 0; r < 32; r += 8)
        t[ty + r][tx] = in[(size_t)(by + ty + r) * D_ + bx + tx];
    __syncthreads();
    #pragma unroll
    for (int r = 0; r < 32; r += 8) {
        float v = t[tx][ty + r];
        const size_t idx = (size_t)(bx + ty + r) * D_ + by + tx;
        __nv_bfloat16 h = __float2bfloat16(v);
        __nv_bfloat16 m = __float2bfloat16(v - __bfloat162float(h));
        oh[idx] = h; om[idx] = m;
    }
}

// ---------------- zero corr ----------------
__global__ void zero_corr_kernel(float* __restrict__ corr)
{
    corr[blockIdx.x * 1024 + threadIdx.x] = 0.0f;
}

// ---------------- top-13 + softmax, one block per batch
__global__ void topk_softmax_kernel(const float* __restrict__ corr,
                                    int* __restrict__ delays, float* __restrict__ w)
{
    const int b   = blockIdx.x;
    const int tid = threadIdx.x;     // 256 threads
    __shared__ float vals[L_];
    __shared__ float rv[256];
    __shared__ int   ri[256];
    __shared__ float topv[TOPK_];
    __shared__ int   topi[TOPK_];

    for (int i = tid; i < L_; i += 256) vals[i] = corr[b * L_ + i];
    __syncthreads();

    for (int sel = 0; sel < TOPK_; sel++) {
        float bv = -FLT_MAX;
        int   bi = 1 << 30;
        for (int i = tid; i < L_; i += 256) {
            float v = vals[i];
            if (v > bv || (v == bv && i < bi)) { bv = v; bi = i; }
        }
        rv[tid] = bv; ri[tid] = bi;
        __syncthreads();
        for (int s = 128; s > 0; s >>= 1) {
            if (tid < s) {
                if (rv[tid+s] > rv[tid] || (rv[tid+s] == rv[tid] && ri[tid+s] < ri[tid])) {
                    rv[tid] = rv[tid+s]; ri[tid] = ri[tid+s];
                }
            }
            __syncthreads();
        }
        if (tid == 0) {
            topv[sel] = rv[0];
            topi[sel] = ri[0];
            vals[ri[0]] = -FLT_MAX;
        }
        __syncthreads();
    }

    if (tid == 0) {
        float mx = topv[0];
        float e[TOPK_], se = 0.0f;
        #pragma unroll
        for (int i = 0; i < TOPK_; i++) { e[i] = expf(topv[i] - mx); se += e[i]; }
        float inv = 1.0f / se;
        #pragma unroll
        for (int i = 0; i < TOPK_; i++) {
            w[b*TOPK_ + i]      = e[i] * inv;
            delays[b*TOPK_ + i] = topi[i];
        }
    }
}

// ------- aggregation: agg[b,t,:] = sum_i w_i * V[b,(t+d_i)%L,:], split output
__global__ void aggregate_kernel(const float* __restrict__ V,
                                 const int* __restrict__ delays,
                                 const float* __restrict__ w,
                                 __nv_bfloat16* __restrict__ Oh,
                                 __nv_bfloat16* __restrict__ Om)
{
    const int t = blockIdx.x;
    const int b = blockIdx.y;
    const int c = threadIdx.x;   // 128 threads -> float4 over D=512
    __shared__ int   sd[TOPK_];
    __shared__ float sw[TOPK_];
    if (c < TOPK_) { sd[c] = delays[b*TOPK_ + c]; sw[c] = w[b*TOPK_ + c]; }
    __syncthreads();

    const float4* V4 = (const float4*)V;
    float4 acc = make_float4(0.f, 0.f, 0.f, 0.f);
    #pragma unroll
    for (int i = 0; i < TOPK_; i++) {
        int row = (t + sd[i]) & (L_ - 1);
        float4 vv = V4[((size_t)(b * L_ + row) * (D_/4)) + c];
        float wi = sw[i];
        acc.x = fmaf(wi, vv.x, acc.x);
        acc.y = fmaf(wi, vv.y, acc.y);
        acc.z = fmaf(wi, vv.z, acc.z);
        acc.w = fmaf(wi, vv.w, acc.w);
    }
    const size_t e = ((size_t)(b * L_ + t) * (D_/4) + c) * 4;
    split2_store(make_float2(acc.x, acc.y), Oh, Om, e);
    split2_store(make_float2(acc.z, acc.w), Oh, Om, e + 2);
}

// ---- season = X - moving_average(X,25) via per-thread sliding window.
// grid (16 segments, B_), 128 threads (one float4 column each), 64 t per block.
__global__ void movavg_kernel(const float* __restrict__ X, float* __restrict__ OutF,
                              __nv_bfloat16* __restrict__ OutH, __nv_bfloat16* __restrict__ OutM)
{
    const int seg = blockIdx.x;
    const int b   = blockIdx.y;
    const int c   = threadIdx.x;   // float4 col 0..127
    const float4* Xb = (const float4*)X + (size_t)b * L_ * 128;
    const int t0 = seg * 64;

    float sx = 0.f, sy = 0.f, sz = 0.f, sw = 0.f;
    const int lo0 = max(t0 - 12, 0), hi0 = min(t0 + 12, L_ - 1);
    for (int ss = lo0; ss <= hi0; ++ss) {
        float4 v = Xb[(size_t)ss * 128 + c];
        sx += v.x; sy += v.y; sz += v.z; sw += v.w;
    }
    for (int t = t0; t < t0 + 64; ++t) {
        const int lo = max(t - 12, 0), hi = min(t + 12, L_ - 1);
        const float inv = 1.0f / (float)(hi - lo + 1);
        float4 xv = Xb[(size_t)t * 128 + c];
        float4 o;
        o.x = xv.x - sx * inv;
        o.y = xv.y - sy * inv;
        o.z = xv.z - sz * inv;
        o.w = xv.w - sw * inv;
        const size_t oi = (size_t)(b * L_ + t) * 128 + c;
        ((float4*)OutF)[oi] = o;
        if (OutH) {
            split2_store(make_float2(o.x, o.y), OutH, OutM, oi * 4);
            split2_store(make_float2(o.z, o.w), OutH, OutM, oi * 4 + 2);
        }
        if (t + 13 <= L_ - 1) {
            float4 v = Xb[(size_t)(t + 13) * 128 + c];
            sx += v.x; sy += v.y; sz += v.z; sw += v.w;
        }
        if (t - 12 >= 0) {
            float4 v = Xb[(size_t)(t - 12) * 128 + c];
            sx -= v.x; sy -= v.y; sz -= v.z; sw -= v.w;
        }
    }
}

// ---------------- host launch ----------------
extern "C" void kernel_launch(void* const* d_in, const int* in_sizes, int n_in,
                              void* d_out, int out_size)
{
    const float* x  = (const float*)d_in[0];
    const float* Wq = (const float*)d_in[1];
    const float* bq = (const float*)d_in[2];
    const float* Wk = (const float*)d_in[3];
    const float* bk = (const float*)d_in[4];
    const float* Wv = (const float*)d_in[5];
    const float* bv = (const float*)d_in[6];
    const float* Wo = (const float*)d_in[7];
    const float* bo = (const float*)d_in[8];
    const float* Wd = (const float*)d_in[9];
    const float* bd = (const float*)d_in[10];
    float* out = (float*)d_out;

    float *v, *x1, *s1, *x2, *corr, *w;
    int* dl;
    __nv_bfloat16 *xh, *xm, *qh, *qm, *kh, *km, *ah, *am, *sh, *sm, *wth, *wtm;
    cudaGetSymbolAddress((void**)&v,    g_v);
    cudaGetSymbolAddress((void**)&x1,   g_x1);
    cudaGetSymbolAddress((void**)&s1,   g_s1);
    cudaGetSymbolAddress((void**)&x2,   g_x2);
    cudaGetSymbolAddress((void**)&corr, g_corr);
    cudaGetSymbolAddress((void**)&dl,   g_delay);
    cudaGetSymbolAddress((void**)&w,    g_w);
    cudaGetSymbolAddress((void**)&xh,   g_xh);  cudaGetSymbolAddress((void**)&xm, g_xm);
    cudaGetSymbolAddress((void**)&qh,   g_qh);  cudaGetSymbolAddress((void**)&qm, g_qm);
    cudaGetSymbolAddress((void**)&kh,   g_kh);  cudaGetSymbolAddress((void**)&km, g_km);
    cudaGetSymbolAddress((void**)&ah,   g_ah);  cudaGetSymbolAddress((void**)&am, g_am);
    cudaGetSymbolAddress((void**)&sh,   g_sh);  cudaGetSymbolAddress((void**)&sm, g_sm);
    cudaGetSymbolAddress((void**)&wth,  g_wth); cudaGetSymbolAddress((void**)&wtm, g_wtm);

    cudaFuncSetAttribute(gemm_bf, cudaFuncAttributeMaxDynamicSharedMemorySize, SMEM_MMA);

    // input splits
    xsplit_kernel<<<NEL_/4/256, 256>>>(x, xh, xm);
    dim3 tT(32, 8), gT(16, 16);
    wtsplit_kernel<<<gT, tT>>>(Wq, wth + 0*D_*D_, wtm + 0*D_*D_);
    wtsplit_kernel<<<gT, tT>>>(Wk, wth + 1*D_*D_, wtm + 1*D_*D_);
    wtsplit_kernel<<<gT, tT>>>(Wv, wth + 2*D_*D_, wtm + 2*D_*D_);
    wtsplit_kernel<<<gT, tT>>>(Wo, wth + 3*D_*D_, wtm + 3*D_*D_);
    wtsplit_kernel<<<gT, tT>>>(Wd, wth + 4*D_*D_, wtm + 4*D_*D_);

    dim3 t256(256);
    dim3 gdense(D_/128, (B_*L_)/128, 1);     // (4, 256, 1)
    dim3 ggram(L_/128, L_/128, B_);          // (8, 8, 32)

    // projections: Q,K -> split bf16 only; V -> fp32
    gemm_bf<<<gdense, t256, SMEM_MMA>>>(xh, xm, wth + 0*D_*D_, wtm + 0*D_*D_,
                                        bq, nullptr, nullptr, qh, qm, nullptr, 0, 0);
    gemm_bf<<<gdense, t256, SMEM_MMA>>>(xh, xm, wth + 1*D_*D_, wtm + 1*D_*D_,
                                        bk, nullptr, nullptr, kh, km, nullptr, 0, 0);
    gemm_bf<<<gdense, t256, SMEM_MMA>>>(xh, xm, wth + 2*D_*D_, wtm + 2*D_*D_,
                                        bv, nullptr, v, nullptr, nullptr, nullptr, 0, 0);

    // Gram + fused circular-diagonal reduce -> corr (G never materialized)
    zero_corr_kernel<<<B_, 1024>>>(corr);
    gemm_bf<<<ggram, t256, SMEM_MMA>>>(qh, qm, kh, km,
                                       nullptr, nullptr, nullptr, nullptr, nullptr, corr,
                                       (size_t)L_*D_, 1);

    // top-13 + softmax per batch
    topk_softmax_kernel<<<B_, 256>>>(corr, dl, w);

    // delay aggregation of V -> split bf16 agg
    dim3 gld(L_, B_);
    aggregate_kernel<<<gld, 128>>>(v, dl, w, ah, am);

    // x1 = agg @ Wo + bo + x
    gemm_bf<<<gdense, t256, SMEM_MMA>>>(ah, am, wth + 3*D_*D_, wtm + 3*D_*D_,
                                        bo, x, x1, nullptr, nullptr, nullptr, 0, 0);

    // s1 = x1 - movavg(x1), plus split bf16 s1
    dim3 gma(16, B_);
    movavg_kernel<<<gma, 128>>>(x1, s1, sh, sm);

    // x2 = s1 @ Wd + bd + s1
    gemm_bf<<<gdense, t256, SMEM_MMA>>>(sh, sm, wth + 4*D_*D_, wtm + 4*D_*D_,
                                        bd, s1, x2, nullptr, nullptr, nullptr, 0, 0);

    // out = x2 - movavg(x2)
    movavg_kernel<<<gma, 128>>>(x2, out, nullptr, nullptr);
}

// round 8
// speedup vs baseline: 2.0794x; 1.0667x over previous
#include <cuda_runtime.h>
#include <cuda_bf16.h>
#include <math.h>
#include <float.h>
#include <stdint.h>

#define B_    32
#define L_    1024
#define D_    512
#define TOPK_ 13
#define NEL_  (B_*L_*D_)
#define NFFT  1024

// ---------------- scratch (static device globals; no allocation) ----------------
__device__ float g_v [NEL_];
__device__ float g_qf[NEL_];
__device__ float g_kf[NEL_];
__device__ float g_x1[NEL_];
__device__ float g_s1[NEL_];
__device__ float g_x2[NEL_];
__device__ float g_corr[B_*L_];
__device__ int   g_delay[B_*TOPK_];
__device__ float g_w[B_*TOPK_];
__device__ float g_S[B_*NFFT*2];         // cross-spectrum accumulator (re,im)
__device__ float2 g_twid[NFFT/2];        // e^{-2*pi*i*j/NFFT}
__device__ __nv_bfloat16 g_xh[NEL_],  g_xm[NEL_];
__device__ __nv_bfloat16 g_ah[NEL_],  g_am[NEL_];
__device__ __nv_bfloat16 g_sh[NEL_],  g_sm[NEL_];
__device__ __nv_bfloat16 g_wth[5*D_*D_], g_wtm[5*D_*D_];

// ================= portable PTX helpers (sm_80+; no arch-'a' features) =========
__device__ __forceinline__ uint32_t smem_to_u32(const void* p) {
    uint32_t a;
    asm("{ .reg .u64 t; cvta.to.shared.u64 t, %1; cvt.u32.u64 %0, t; }" : "=r"(a) : "l"(p));
    return a;
}
#define LDMX4(r0,r1,r2,r3,addr) \
    asm volatile("ldmatrix.sync.aligned.m8n8.x4.shared.b16 {%0,%1,%2,%3}, [%4];" \
        : "=r"(r0), "=r"(r1), "=r"(r2), "=r"(r3) : "r"(addr))
#define MMA16816(c,a,b) \
    asm volatile("mma.sync.aligned.m16n8k16.row.col.f32.bf16.bf16.f32 " \
        "{%0,%1,%2,%3},{%4,%5,%6,%7},{%8,%9},{%0,%1,%2,%3};" \
        : "+f"((c)[0]), "+f"((c)[1]), "+f"((c)[2]), "+f"((c)[3]) \
        : "r"((a)[0]), "r"((a)[1]), "r"((a)[2]), "r"((a)[3]), "r"((b)[0]), "r"((b)[1]))
#define CP16(dst, src) \
    asm volatile("cp.async.cg.shared.global [%0], [%1], 16;" :: "r"(dst), "l"(src) : "memory")
#define CPCOMMIT() asm volatile("cp.async.commit_group;" ::: "memory")
#define CPWAIT1()  asm volatile("cp.async.wait_group 1;" ::: "memory")
#define CPWAIT0()  asm volatile("cp.async.wait_group 0;" ::: "memory")

__device__ __forceinline__ void split2_store(float2 v, __nv_bfloat16* H, __nv_bfloat16* M, size_t e) {
    __nv_bfloat162 h = __float22bfloat162_rn(v);
    float2 r = make_float2(v.x - __bfloat162float(h.x), v.y - __bfloat162float(h.y));
    __nv_bfloat162 m = __float22bfloat162_rn(r);
    *(__nv_bfloat162*)(H + e) = h;
    *(__nv_bfloat162*)(M + e) = m;
}

// ================= bf16 split-operand MMA GEMM: C = A*B^T (+bias)(+res) =======
// A(h/m),B(h/m): [rows,512] bf16 NT. M=32768, N=512, K=512 fixed.
// CTA 128x128, BK=32, 8 warps (warp tile 32m x 64n), 3-product accumulate.
#define ROWB   80
#define TILEB  (128*ROWB)      // 10240
#define STAGEB (4*TILEB)       // 40960
#define SMEM_MMA (2*STAGEB)    // 81920

__global__ __launch_bounds__(256, 2)
void gemm_bf(const __nv_bfloat16* __restrict__ Ah, const __nv_bfloat16* __restrict__ Am,
             const __nv_bfloat16* __restrict__ Bh, const __nv_bfloat16* __restrict__ Bm,
             const float* __restrict__ bias, const float* __restrict__ res,
             float* __restrict__ outF)
{
    extern __shared__ __align__(128) char smem[];
    const int tid  = threadIdx.x;
    const int wid  = tid >> 5;
    const int lane = tid & 31;
    const int m0 = blockIdx.y * 128;
    const int n0 = blockIdx.x * 128;
    const uint32_t sb = smem_to_u32(smem);

    const int g  = lane >> 2, tg = lane & 3;
    const int wm = wid >> 1,  wn = wid & 1;

    float acc[2][8][4];
    #pragma unroll
    for (int i = 0; i < 2; i++)
        #pragma unroll
        for (int j = 0; j < 8; j++)
            #pragma unroll
            for (int r = 0; r < 4; r++) acc[i][j][r] = 0.0f;

    // ldmatrix x4 lane mapping (validated R6/R7): groups (0,0),(8,0),(0,+8),(8,+8)
    const int asel = lane >> 3, ar = lane & 7;
    const int rq = (asel & 1) * 8 + ar;     // row offset within 16
    const int kq = (asel >> 1) * 8;         // k offset within 16

    // cp.async mapping
    const int crow = tid >> 1;
    const int coff = (tid & 1);
    const __nv_bfloat16* Ahp = Ah + (size_t)(m0 + crow) * D_ + coff * 16;
    const __nv_bfloat16* Amp = Am + (size_t)(m0 + crow) * D_ + coff * 16;
    const __nv_bfloat16* Bhp = Bh + (size_t)(n0 + crow) * D_ + coff * 16;
    const __nv_bfloat16* Bmp = Bm + (size_t)(n0 + crow) * D_ + coff * 16;
    const uint32_t drow = (uint32_t)(crow * ROWB + coff * 32);

    auto issue = [&](int c, int s) {
        const uint32_t db = sb + s * STAGEB + drow;
        const size_t go = (size_t)c * 32;
        CP16(db + 0*TILEB,      Ahp + go);
        CP16(db + 0*TILEB + 16, Ahp + go + 8);
        CP16(db + 1*TILEB,      Amp + go);
        CP16(db + 1*TILEB + 16, Amp + go + 8);
        CP16(db + 2*TILEB,      Bhp + go);
        CP16(db + 2*TILEB + 16, Bhp + go + 8);
        CP16(db + 3*TILEB,      Bmp + go);
        CP16(db + 3*TILEB + 16, Bmp + go + 8);
    };

    issue(0, 0); CPCOMMIT();

    for (int c = 0; c < 16; ++c) {
        const int s = c & 1;
        if (c < 15) { issue(c + 1, s ^ 1); CPCOMMIT(); CPWAIT1(); }
        else        { CPWAIT0(); }
        __syncthreads();

        const uint32_t aHi  = sb + s*STAGEB;
        const uint32_t aMid = aHi + TILEB;
        const uint32_t bHi  = aHi + 2*TILEB;
        const uint32_t bMid = aHi + 3*TILEB;

        #pragma unroll
        for (int kk = 0; kk < 32; kk += 16) {
            uint32_t ah[2][4], am[2][4], bh[8][2];
            #pragma unroll
            for (int mt = 0; mt < 2; mt++) {
                const uint32_t ao = (uint32_t)((wm*32 + mt*16 + rq)*ROWB + (kk + kq)*2);
                LDMX4(ah[mt][0], ah[mt][1], ah[mt][2], ah[mt][3], aHi  + ao);
                LDMX4(am[mt][0], am[mt][1], am[mt][2], am[mt][3], aMid + ao);
            }
            // B hi fragments: 4 x LDMX4, each covering 2 n8-tiles x full k16
            #pragma unroll
            for (int np = 0; np < 4; np++) {
                uint32_t r0, r1, r2, r3;
                const uint32_t bo = (uint32_t)((wn*64 + np*16 + rq)*ROWB + (kk + kq)*2);
                LDMX4(r0, r1, r2, r3, bHi + bo);
                bh[2*np][0]   = r0; bh[2*np][1]   = r2;
                bh[2*np+1][0] = r1; bh[2*np+1][1] = r3;
            }
            // pass 1: hi*hi
            #pragma unroll
            for (int nt = 0; nt < 8; nt++)
                #pragma unroll
                for (int mt = 0; mt < 2; mt++)
                    MMA16816(acc[mt][nt], ah[mt], bh[nt]);
            // pass 2: mid_A * hi_B
            #pragma unroll
            for (int nt = 0; nt < 8; nt++)
                #pragma unroll
                for (int mt = 0; mt < 2; mt++)
                    MMA16816(acc[mt][nt], am[mt], bh[nt]);
            // pass 3: hi_A * mid_B (load bm 4 tiles at a time via 2 x LDMX4)
            #pragma unroll
            for (int ng = 0; ng < 2; ng++) {
                uint32_t bm2[4][2];
                #pragma unroll
                for (int np = 0; np < 2; np++) {
                    uint32_t r0, r1, r2, r3;
                    const uint32_t bo = (uint32_t)((wn*64 + (ng*2+np)*16 + rq)*ROWB + (kk + kq)*2);
                    LDMX4(r0, r1, r2, r3, bMid + bo);
                    bm2[2*np][0]   = r0; bm2[2*np][1]   = r2;
                    bm2[2*np+1][0] = r1; bm2[2*np+1][1] = r3;
                }
                #pragma unroll
                for (int j = 0; j < 4; j++)
                    #pragma unroll
                    for (int mt = 0; mt < 2; mt++)
                        MMA16816(acc[mt][ng*4 + j], ah[mt], bm2[j]);
            }
        }
        __syncthreads();
    }

    // ---- epilogue: bias/res fused, fp32 out ----
    #pragma unroll
    for (int mt = 0; mt < 2; mt++) {
        const int row0 = m0 + wm*32 + mt*16 + g;
        #pragma unroll
        for (int nt = 0; nt < 8; nt++) {
            const int col = n0 + wn*64 + nt*8 + tg*2;
            float b0 = 0.f, b1 = 0.f;
            if (bias) { b0 = bias[col]; b1 = bias[col + 1]; }
            float2 v0 = make_float2(acc[mt][nt][0] + b0, acc[mt][nt][1] + b1);
            float2 v1 = make_float2(acc[mt][nt][2] + b0, acc[mt][nt][3] + b1);
            const size_t i0 = (size_t)row0 * D_ + col;
            const size_t i1 = (size_t)(row0 + 8) * D_ + col;
            if (res) {
                float2 r0 = *(const float2*)&res[i0];
                float2 r1 = *(const float2*)&res[i1];
                v0.x += r0.x; v0.y += r0.y;
                v1.x += r1.x; v1.y += r1.y;
            }
            *(float2*)&outF[i0] = v0;
            *(float2*)&outF[i1] = v1;
        }
    }
}

// ---------------- x -> hi/mid bf16 split ----------------
__global__ void xsplit_kernel(const float* __restrict__ X,
                              __nv_bfloat16* __restrict__ H, __nv_bfloat16* __restrict__ M)
{
    const size_t i = (size_t)blockIdx.x * blockDim.x + threadIdx.x;
    float4 v = ((const float4*)X)[i];
    split2_store(make_float2(v.x, v.y), H, M, i*4);
    split2_store(make_float2(v.z, v.w), H, M, i*4 + 2);
}

// ------- merged weight transpose + split (grid.z selects weight) ---------------
__global__ void wtsplit_kernel(const float* __restrict__ W0, const float* __restrict__ W1,
                               const float* __restrict__ W2, const float* __restrict__ W3,
                               const float* __restrict__ W4,
                               __nv_bfloat16* __restrict__ oh, __nv_bfloat16* __restrict__ om)
{
    const int z = blockIdx.z;
    const float* in = (z == 0) ? W0 : (z == 1) ? W1 : (z == 2) ? W2 : (z == 3) ? W3 : W4;
    oh += (size_t)z * D_ * D_;
    om += (size_t)z * D_ * D_;
    __shared__ float t[32][33];
    const int bx = blockIdx.x * 32, by = blockIdx.y * 32;
    const int tx = threadIdx.x, ty = threadIdx.y;   // 32 x 8
    #pragma unroll
    for (int r = 0; r < 32; r += 8)
        t[ty + r][tx] = in[(size_t)(by + ty + r) * D_ + bx + tx];
    __syncthreads();
    #pragma unroll
    for (int r = 0; r < 32; r += 8) {
        float v = t[tx][ty + r];
        const size_t idx = (size_t)(bx + ty + r) * D_ + by + tx;
        __nv_bfloat16 h = __float2bfloat16(v);
        __nv_bfloat16 m = __float2bfloat16(v - __bfloat162float(h));
        oh[idx] = h; om[idx] = m;
    }
}

// ---------------- FFT machinery ----------------
__global__ void twiddle_kernel()   // exact twiddles via fp64
{
    int j = blockIdx.x * 256 + threadIdx.x;   // grid 2 x 256 -> 512
    double a = -2.0 * 3.14159265358979323846 * (double)j / (double)NFFT;
    g_twid[j] = make_float2((float)cos(a), (float)sin(a));
}
__global__ void zeroS_kernel() { g_S[blockIdx.x * 1024 + threadIdx.x] = 0.0f; }

__device__ __forceinline__ int brev10(int x) { return (int)(__brev((uint32_t)x) >> 22); }

// forward: Z_c = FFT(q_c + i*k_c) for 8 channels; unpack; accumulate cross-spectrum.
// grid (D_/8, B_), 256 threads, 64KB dynamic smem.
__global__ __launch_bounds__(256)
void fft_fwd_kernel(const float* __restrict__ Q, const float* __restrict__ K)
{
    extern __shared__ __align__(16) float2 Z[];    // 8 * 1024
    __shared__ float2 tw[NFFT/2];
    const int tid = threadIdx.x;
    const int c0  = blockIdx.x * 8;
    const int b   = blockIdx.y;

    for (int i = tid; i < NFFT/2; i += 256) tw[i] = g_twid[i];

    const float* Qb = Q + (size_t)b * L_ * D_ + c0;
    const float* Kb = K + (size_t)b * L_ * D_ + c0;
    for (int i = tid; i < 8 * NFFT; i += 256) {
        const int t = i >> 3, cc = i & 7;
        Z[cc * NFFT + t] = make_float2(Qb[(size_t)t * D_ + cc], Kb[(size_t)t * D_ + cc]);
    }
    __syncthreads();

    // DIF radix-2: natural in -> bit-reversed out
    #pragma unroll
    for (int st = 0; st < 10; ++st) {
        const int m = 512 >> st;
        for (int i = tid; i < 8 * 512; i += 256) {
            const int col = i >> 9;
            const int bi  = i & 511;
            const int j   = bi & (m - 1);
            const int gg  = bi >> (9 - st);
            const int base = col * NFFT + (gg << (10 - st)) + j;
            float2 u = Z[base], v = Z[base + m];
            float2 w = tw[j << st];
            float2 d = make_float2(u.x - v.x, u.y - v.y);
            Z[base]     = make_float2(u.x + v.x, u.y + v.y);
            Z[base + m] = make_float2(d.x*w.x - d.y*w.y, d.x*w.y + d.y*w.x);
        }
        __syncthreads();
    }

    // unpack Qhat/Khat, accumulate S[f] += sum_c Qhat * conj(Khat)
    for (int f = tid; f < NFFT; f += 256) {
        const int p  = brev10(f);
        const int pn = brev10((NFFT - f) & (NFFT - 1));
        float sx = 0.f, sy = 0.f;
        #pragma unroll
        for (int cc = 0; cc < 8; cc++) {
            float2 z1 = Z[cc * NFFT + p];
            float2 z2 = Z[cc * NFFT + pn];
            float Qx = 0.5f * (z1.x + z2.x), Qy = 0.5f * (z1.y - z2.y);
            float wx = z1.x - z2.x,          wy = z1.y + z2.y;   // z1 - conj(z2)
            float Kx = 0.5f * wy,            Ky = -0.5f * wx;    // /(2i)
            sx += Qx * Kx + Qy * Ky;          // Re(Q * conj(K))
            sy += Qy * Kx - Qx * Ky;          // Im(Q * conj(K))
        }
        atomicAdd(&g_S[(b * NFFT + f) * 2    ], sx);
        atomicAdd(&g_S[(b * NFFT + f) * 2 + 1], sy);
    }
}

// inverse: corr[b,tau] = (1/(N*D)) * sum_f S[f] e^{+2pi i f tau/N}. one block per b.
__global__ __launch_bounds__(256)
void fft_inv_kernel(float* __restrict__ corr)
{
    __shared__ float2 Zs[NFFT];
    __shared__ float2 tw[NFFT/2];
    const int tid = threadIdx.x;
    const int b   = blockIdx.x;
    for (int i = tid; i < NFFT/2; i += 256) tw[i] = g_twid[i];
    for (int i = tid; i < NFFT; i += 256)
        Zs[i] = make_float2(g_S[(b * NFFT + i) * 2], g_S[(b * NFFT + i) * 2 + 1]);
    __syncthreads();

    #pragma unroll
    for (int st = 0; st < 10; ++st) {
        const int m = 512 >> st;
        for (int bi = tid; bi < 512; bi += 256) {
            const int j  = bi & (m - 1);
            const int gg = bi >> (9 - st);
            const int base = (gg << (10 - st)) + j;
            float2 u = Zs[base], v = Zs[base + m];
            float2 w = tw[j << st];                 // use conj(w) for inverse
            float2 d = make_float2(u.x - v.x, u.y - v.y);
            Zs[base]     = make_float2(u.x + v.x, u.y + v.y);
            Zs[base + m] = make_float2(d.x*w.x + d.y*w.y, d.y*w.x - d.x*w.y);
        }
        __syncthreads();
    }
    const float scale = 1.0f / ((float)NFFT * (float)D_);
    for (int p = tid; p < NFFT; p += 256)
        corr[b * L_ + brev10(p)] = Zs[p].x * scale;
}

// ---------------- top-13 + softmax, one block per batch
__global__ void topk_softmax_kernel(const float* __restrict__ corr,
                                    int* __restrict__ delays, float* __restrict__ w)
{
    const int b   = blockIdx.x;
    const int tid = threadIdx.x;     // 256 threads
    __shared__ float vals[L_];
    __shared__ float rv[256];
    __shared__ int   ri[256];
    __shared__ float topv[TOPK_];
    __shared__ int   topi[TOPK_];

    for (int i = tid; i < L_; i += 256) vals[i] = corr[b * L_ + i];
    __syncthreads();

    for (int sel = 0; sel < TOPK_; sel++) {
        float bv = -FLT_MAX;
        int   bi = 1 << 30;
        for (int i = tid; i < L_; i += 256) {
            float v = vals[i];
            if (v > bv || (v == bv && i < bi)) { bv = v; bi = i; }
        }
        rv[tid] = bv; ri[tid] = bi;
        __syncthreads();
        for (int s = 128; s > 0; s >>= 1) {
            if (tid < s) {
                if (rv[tid+s] > rv[tid] || (rv[tid+s] == rv[tid] && ri[tid+s] < ri[tid])) {
                    rv[tid] = rv[tid+s]; ri[tid] = ri[tid+s];
                }
            }
            __syncthreads();
        }
        if (tid == 0) {
            topv[sel] = rv[0];
            topi[sel] = ri[0];
            vals[ri[0]] = -FLT_MAX;
        }
        __syncthreads();
    }

    if (tid == 0) {
        float mx = topv[0];
        float e[TOPK_], se = 0.0f;
        #pragma unroll
        for (int i = 0; i < TOPK_; i++) { e[i] = expf(topv[i] - mx); se += e[i]; }
        float inv = 1.0f / se;
        #pragma unroll
        for (int i = 0; i < TOPK_; i++) {
            w[b*TOPK_ + i]      = e[i] * inv;
            delays[b*TOPK_ + i] = topi[i];
        }
    }
}

// ------- aggregation: agg[b,t,:] = sum_i w_i * V[b,(t+d_i)%L,:], split output
__global__ void aggregate_kernel(const float* __restrict__ V,
                                 const int* __restrict__ delays,
                                 const float* __restrict__ w,
                                 __nv_bfloat16* __restrict__ Oh,
                                 __nv_bfloat16* __restrict__ Om)
{
    const int t = blockIdx.x;
    const int b = blockIdx.y;
    const int c = threadIdx.x;   // 128 threads -> float4 over D=512
    __shared__ int   sd[TOPK_];
    __shared__ float sw[TOPK_];
    if (c < TOPK_) { sd[c] = delays[b*TOPK_ + c]; sw[c] = w[b*TOPK_ + c]; }
    __syncthreads();

    const float4* V4 = (const float4*)V;
    float4 acc = make_float4(0.f, 0.f, 0.f, 0.f);
    #pragma unroll
    for (int i = 0; i < TOPK_; i++) {
        int row = (t + sd[i]) & (L_ - 1);
        float4 vv = V4[((size_t)(b * L_ + row) * (D_/4)) + c];
        float wi = sw[i];
        acc.x = fmaf(wi, vv.x, acc.x);
        acc.y = fmaf(wi, vv.y, acc.y);
        acc.z = fmaf(wi, vv.z, acc.z);
        acc.w = fmaf(wi, vv.w, acc.w);
    }
    const size_t e = ((size_t)(b * L_ + t) * (D_/4) + c) * 4;
    split2_store(make_float2(acc.x, acc.y), Oh, Om, e);
    split2_store(make_float2(acc.z, acc.w), Oh, Om, e + 2);
}

// ---- season = X - moving_average(X,25) via per-thread sliding window ----------
__global__ void movavg_kernel(const float* __restrict__ X, float* __restrict__ OutF,
                              __nv_bfloat16* __restrict__ OutH, __nv_bfloat16* __restrict__ OutM)
{
    const int seg = blockIdx.x;
    const int b   = blockIdx.y;
    const int c   = threadIdx.x;
    const float4* Xb = (const float4*)X + (size_t)b * L_ * 128;
    const int t0 = seg * 64;

    float sx = 0.f, sy = 0.f, sz = 0.f, sw = 0.f;
    const int lo0 = max(t0 - 12, 0), hi0 = min(t0 + 12, L_ - 1);
    for (int ss = lo0; ss <= hi0; ++ss) {
        float4 v = Xb[(size_t)ss * 128 + c];
        sx += v.x; sy += v.y; sz += v.z; sw += v.w;
    }
    for (int t = t0; t < t0 + 64; ++t) {
        const int lo = max(t - 12, 0), hi = min(t + 12, L_ - 1);
        const float inv = 1.0f / (float)(hi - lo + 1);
        float4 xv = Xb[(size_t)t * 128 + c];
        float4 o;
        o.x = xv.x - sx * inv;
        o.y = xv.y - sy * inv;
        o.z = xv.z - sz * inv;
        o.w = xv.w - sw * inv;
        const size_t oi = (size_t)(b * L_ + t) * 128 + c;
        ((float4*)OutF)[oi] = o;
        if (OutH) {
            split2_store(make_float2(o.x, o.y), OutH, OutM, oi * 4);
            split2_store(make_float2(o.z, o.w), OutH, OutM, oi * 4 + 2);
        }
        if (t + 13 <= L_ - 1) {
            float4 v = Xb[(size_t)(t + 13) * 128 + c];
            sx += v.x; sy += v.y; sz += v.z; sw += v.w;
        }
        if (t - 12 >= 0) {
            float4 v = Xb[(size_t)(t - 12) * 128 + c];
            sx -= v.x; sy -= v.y; sz -= v.z; sw -= v.w;
        }
    }
}

// ---------------- host launch ----------------
extern "C" void kernel_launch(void* const* d_in, const int* in_sizes, int n_in,
                              void* d_out, int out_size)
{
    const float* x  = (const float*)d_in[0];
    const float* Wq = (const float*)d_in[1];
    const float* bq = (const float*)d_in[2];
    const float* Wk = (const float*)d_in[3];
    const float* bk = (const float*)d_in[4];
    const float* Wv = (const float*)d_in[5];
    const float* bv = (const float*)d_in[6];
    const float* Wo = (const float*)d_in[7];
    const float* bo = (const float*)d_in[8];
    const float* Wd = (const float*)d_in[9];
    const float* bd = (const float*)d_in[10];
    float* out = (float*)d_out;

    float *v, *qf, *kf, *x1, *s1, *x2, *corr, *w;
    int* dl;
    __nv_bfloat16 *xh, *xm, *ah, *am, *sh, *sm, *wth, *wtm;
    cudaGetSymbolAddress((void**)&v,    g_v);
    cudaGetSymbolAddress((void**)&qf,   g_qf);
    cudaGetSymbolAddress((void**)&kf,   g_kf);
    cudaGetSymbolAddress((void**)&x1,   g_x1);
    cudaGetSymbolAddress((void**)&s1,   g_s1);
    cudaGetSymbolAddress((void**)&x2,   g_x2);
    cudaGetSymbolAddress((void**)&corr, g_corr);
    cudaGetSymbolAddress((void**)&dl,   g_delay);
    cudaGetSymbolAddress((void**)&w,    g_w);
    cudaGetSymbolAddress((void**)&xh,   g_xh);  cudaGetSymbolAddress((void**)&xm, g_xm);
    cudaGetSymbolAddress((void**)&ah,   g_ah);  cudaGetSymbolAddress((void**)&am, g_am);
    cudaGetSymbolAddress((void**)&sh,   g_sh);  cudaGetSymbolAddress((void**)&sm, g_sm);
    cudaGetSymbolAddress((void**)&wth,  g_wth); cudaGetSymbolAddress((void**)&wtm, g_wtm);

    cudaFuncSetAttribute(gemm_bf, cudaFuncAttributeMaxDynamicSharedMemorySize, SMEM_MMA);
    cudaFuncSetAttribute(fft_fwd_kernel, cudaFuncAttributeMaxDynamicSharedMemorySize, 8*NFFT*8);

    // input splits + twiddles
    xsplit_kernel<<<NEL_/4/256, 256>>>(x, xh, xm);
    dim3 tT(32, 8), gT(16, 16, 5);
    wtsplit_kernel<<<gT, tT>>>(Wq, Wk, Wv, Wo, Wd, wth, wtm);
    twiddle_kernel<<<2, 256>>>();

    dim3 t256(256);
    dim3 gdense(D_/128, (B_*L_)/128);     // (4, 256)

    // projections (fp32 outputs)
    gemm_bf<<<gdense, t256, SMEM_MMA>>>(xh, xm, wth + 0*D_*D_, wtm + 0*D_*D_, bq, nullptr, qf);
    gemm_bf<<<gdense, t256, SMEM_MMA>>>(xh, xm, wth + 1*D_*D_, wtm + 1*D_*D_, bk, nullptr, kf);
    gemm_bf<<<gdense, t256, SMEM_MMA>>>(xh, xm, wth + 2*D_*D_, wtm + 2*D_*D_, bv, nullptr, v);

    // FFT autocorrelation -> corr
    zeroS_kernel<<<B_*2, 1024>>>();
    dim3 gfft(D_/8, B_);
    fft_fwd_kernel<<<gfft, 256, 8*NFFT*8>>>(qf, kf);
    fft_inv_kernel<<<B_, 256>>>(corr);

    // top-13 + softmax per batch
    topk_softmax_kernel<<<B_, 256>>>(corr, dl, w);

    // delay aggregation of V -> split bf16 agg
    dim3 gld(L_, B_);
    aggregate_kernel<<<gld, 128>>>(v, dl, w, ah, am);

    // x1 = agg @ Wo + bo + x
    gemm_bf<<<gdense, t256, SMEM_MMA>>>(ah, am, wth + 3*D_*D_, wtm + 3*D_*D_, bo, x, x1);

    // s1 = x1 - movavg(x1), plus split bf16 s1
    dim3 gma(16, B_);
    movavg_kernel<<<gma, 128>>>(x1, s1, sh, sm);

    // x2 = s1 @ Wd + bd + s1
    gemm_bf<<<gdense, t256, SMEM_MMA>>>(sh, sm, wth + 4*D_*D_, wtm + 4*D_*D_, bd, s1, x2);

    // out = x2 - movavg(x2)
    movavg_kernel<<<gma, 128>>>(x2, out, nullptr, nullptr);
}

// round 10
// speedup vs baseline: 2.5434x; 1.2231x over previous
#include <cuda_runtime.h>
#include <cuda_fp16.h>
#include <math.h>
#include <float.h>
#include <stdint.h>

#define B_    32
#define L_    1024
#define D_    512
#define TOPK_ 13
#define NEL_  (B_*L_*D_)
#define NFFT  1024

// ---------------- scratch (static device globals; no allocation) ----------------
__device__ float g_v [NEL_];
__device__ float g_qf[NEL_];
__device__ float g_kf[NEL_];
__device__ float g_x1[NEL_];
__device__ float g_s1[NEL_];
__device__ float g_x2[NEL_];
__device__ float g_corr[B_*L_];
__device__ int   g_delay[B_*TOPK_];
__device__ float g_w[B_*TOPK_];
__device__ float g_S[B_*NFFT*2];         // cross-spectrum accumulator (re,im)
__device__ float2 g_twid[NFFT/2];        // e^{-2*pi*i*j/NFFT}
__device__ __half g_xh[NEL_],  g_xm[NEL_];
__device__ __half g_ah[NEL_],  g_am[NEL_];
__device__ __half g_sh[NEL_],  g_sm[NEL_];
__device__ __half g_wth[5*D_*D_];        // only hi needed for B side

// ================= portable PTX helpers (sm_80+; no arch-'a' features) =========
__device__ __forceinline__ uint32_t smem_to_u32(const void* p) {
    uint32_t a;
    asm("{ .reg .u64 t; cvta.to.shared.u64 t, %1; cvt.u32.u64 %0, t; }" : "=r"(a) : "l"(p));
    return a;
}
#define LDMX4(r0,r1,r2,r3,addr) \
    asm volatile("ldmatrix.sync.aligned.m8n8.x4.shared.b16 {%0,%1,%2,%3}, [%4];" \
        : "=r"(r0), "=r"(r1), "=r"(r2), "=r"(r3) : "r"(addr))
#define MMA16816(c,a,b) \
    asm volatile("mma.sync.aligned.m16n8k16.row.col.f32.f16.f16.f32 " \
        "{%0,%1,%2,%3},{%4,%5,%6,%7},{%8,%9},{%0,%1,%2,%3};" \
        : "+f"((c)[0]), "+f"((c)[1]), "+f"((c)[2]), "+f"((c)[3]) \
        : "r"((a)[0]), "r"((a)[1]), "r"((a)[2]), "r"((a)[3]), "r"((b)[0]), "r"((b)[1]))
#define CP16(dst, src) \
    asm volatile("cp.async.cg.shared.global [%0], [%1], 16;" :: "r"(dst), "l"(src) : "memory")
#define CPCOMMIT() asm volatile("cp.async.commit_group;" ::: "memory")
#define CPWAIT1()  asm volatile("cp.async.wait_group 1;" ::: "memory")
#define CPWAIT0()  asm volatile("cp.async.wait_group 0;" ::: "memory")

// split fp32 pair -> fp16 hi + fp16 mid
__device__ __forceinline__ void split2_store(float2 v, __half* H, __half* M, size_t e) {
    __half2 h = __float22half2_rn(v);
    float2 r = make_float2(v.x - __half2float(h.x), v.y - __half2float(h.y));
    __half2 m = __float22half2_rn(r);
    *(__half2*)(H + e) = h;
    *(__half2*)(M + e) = m;
}

// ========= fp16 2-product MMA GEMM: C = A*B^T (+bias)(+res) ===================
// A(h/m): [M,512] fp16 NT; B(h): [N,512] fp16 NT. Product = Ah*Bh + Am*Bh.
// CTA 128x128, BK=32, 8 warps (warp tile 32m x 64n).
#define ROWB   80
#define TILEB  (128*ROWB)      // 10240
#define STAGEB (3*TILEB)       // 30720
#define SMEM_MMA (2*STAGEB)    // 61440

__global__ __launch_bounds__(256, 2)
void gemm_hf(const __half* __restrict__ Ah, const __half* __restrict__ Am,
             const __half* __restrict__ Bh,
             const float* __restrict__ bias, const float* __restrict__ res,
             float* __restrict__ outF)
{
    extern __shared__ __align__(128) char smem[];
    const int tid  = threadIdx.x;
    const int wid  = tid >> 5;
    const int lane = tid & 31;
    const int m0 = blockIdx.y * 128;
    const int n0 = blockIdx.x * 128;
    const uint32_t sb = smem_to_u32(smem);

    const int g  = lane >> 2, tg = lane & 3;
    const int wm = wid >> 1,  wn = wid & 1;

    float acc[2][8][4];
    #pragma unroll
    for (int i = 0; i < 2; i++)
        #pragma unroll
        for (int j = 0; j < 8; j++)
            #pragma unroll
            for (int r = 0; r < 4; r++) acc[i][j][r] = 0.0f;

    // ldmatrix x4 lane mapping (validated R6-R8)
    const int asel = lane >> 3, ar = lane & 7;
    const int rq = (asel & 1) * 8 + ar;
    const int kq = (asel >> 1) * 8;

    // cp.async mapping
    const int crow = tid >> 1;
    const int coff = (tid & 1);
    const __half* Ahp = Ah + (size_t)(m0 + crow) * D_ + coff * 16;
    const __half* Amp = Am + (size_t)(m0 + crow) * D_ + coff * 16;
    const __half* Bhp = Bh + (size_t)(n0 + crow) * D_ + coff * 16;
    const uint32_t drow = (uint32_t)(crow * ROWB + coff * 32);

    auto issue = [&](int c, int s) {
        const uint32_t db = sb + s * STAGEB + drow;
        const size_t go = (size_t)c * 32;
        CP16(db + 0*TILEB,      Ahp + go);
        CP16(db + 0*TILEB + 16, Ahp + go + 8);
        CP16(db + 1*TILEB,      Amp + go);
        CP16(db + 1*TILEB + 16, Amp + go + 8);
        CP16(db + 2*TILEB,      Bhp + go);
        CP16(db + 2*TILEB + 16, Bhp + go + 8);
    };

    issue(0, 0); CPCOMMIT();

    for (int c = 0; c < 16; ++c) {
        const int s = c & 1;
        if (c < 15) { issue(c + 1, s ^ 1); CPCOMMIT(); CPWAIT1(); }
        else        { CPWAIT0(); }
        __syncthreads();

        const uint32_t aHi  = sb + s*STAGEB;
        const uint32_t aMid = aHi + TILEB;
        const uint32_t bHi  = aHi + 2*TILEB;

        #pragma unroll
        for (int kk = 0; kk < 32; kk += 16) {
            uint32_t ah[2][4], am[2][4], bh[8][2];
            #pragma unroll
            for (int mt = 0; mt < 2; mt++) {
                const uint32_t ao = (uint32_t)((wm*32 + mt*16 + rq)*ROWB + (kk + kq)*2);
                LDMX4(ah[mt][0], ah[mt][1], ah[mt][2], ah[mt][3], aHi  + ao);
                LDMX4(am[mt][0], am[mt][1], am[mt][2], am[mt][3], aMid + ao);
            }
            #pragma unroll
            for (int np = 0; np < 4; np++) {
                uint32_t r0, r1, r2, r3;
                const uint32_t bo = (uint32_t)((wn*64 + np*16 + rq)*ROWB + (kk + kq)*2);
                LDMX4(r0, r1, r2, r3, bHi + bo);
                bh[2*np][0]   = r0; bh[2*np][1]   = r2;
                bh[2*np+1][0] = r1; bh[2*np+1][1] = r3;
            }
            // pass 1: hi_A * hi_B (acc reuse distance 16)
            #pragma unroll
            for (int nt = 0; nt < 8; nt++)
                #pragma unroll
                for (int mt = 0; mt < 2; mt++)
                    MMA16816(acc[mt][nt], ah[mt], bh[nt]);
            // pass 2: mid_A * hi_B
            #pragma unroll
            for (int nt = 0; nt < 8; nt++)
                #pragma unroll
                for (int mt = 0; mt < 2; mt++)
                    MMA16816(acc[mt][nt], am[mt], bh[nt]);
        }
        __syncthreads();
    }

    // ---- epilogue: bias/res fused, fp32 out ----
    #pragma unroll
    for (int mt = 0; mt < 2; mt++) {
        const int row0 = m0 + wm*32 + mt*16 + g;
        #pragma unroll
        for (int nt = 0; nt < 8; nt++) {
            const int col = n0 + wn*64 + nt*8 + tg*2;
            float b0 = 0.f, b1 = 0.f;
            if (bias) { b0 = bias[col]; b1 = bias[col + 1]; }
            float2 v0 = make_float2(acc[mt][nt][0] + b0, acc[mt][nt][1] + b1);
            float2 v1 = make_float2(acc[mt][nt][2] + b0, acc[mt][nt][3] + b1);
            const size_t i0 = (size_t)row0 * D_ + col;
            const size_t i1 = (size_t)(row0 + 8) * D_ + col;
            if (res) {
                float2 r0 = *(const float2*)&res[i0];
                float2 r1 = *(const float2*)&res[i1];
                v0.x += r0.x; v0.y += r0.y;
                v1.x += r1.x; v1.y += r1.y;
            }
            *(float2*)&outF[i0] = v0;
            *(float2*)&outF[i1] = v1;
        }
    }
}

// ---------------- x -> hi/mid fp16 split ----------------
__global__ void xsplit_kernel(const float* __restrict__ X,
                              __half* __restrict__ H, __half* __restrict__ M)
{
    const size_t i = (size_t)blockIdx.x * blockDim.x + threadIdx.x;
    float4 v = ((const float4*)X)[i];
    split2_store(make_float2(v.x, v.y), H, M, i*4);
    split2_store(make_float2(v.z, v.w), H, M, i*4 + 2);
}

// ------- merged weight transpose + fp16 hi (grid.z selects weight) -------------
__global__ void wtsplit_kernel(const float* __restrict__ W0, const float* __restrict__ W1,
                               const float* __restrict__ W2, const float* __restrict__ W3,
                               const float* __restrict__ W4,
                               __half* __restrict__ oh)
{
    const int z = blockIdx.z;
    const float* in = (z == 0) ? W0 : (z == 1) ? W1 : (z == 2) ? W2 : (z == 3) ? W3 : W4;
    oh += (size_t)z * D_ * D_;
    __shared__ float t[32][33];
    const int bx = blockIdx.x * 32, by = blockIdx.y * 32;
    const int tx = threadIdx.x, ty = threadIdx.y;   // 32 x 8
    #pragma unroll
    for (int r = 0; r < 32; r += 8)
        t[ty + r][tx] = in[(size_t)(by + ty + r) * D_ + bx + tx];
    __syncthreads();
    #pragma unroll
    for (int r = 0; r < 32; r += 8) {
        float v = t[tx][ty + r];
        oh[(size_t)(bx + ty + r) * D_ + by + tx] = __float2half_rn(v);
    }
}

// ---------------- FFT machinery ----------------
__global__ void twiddle_kernel()
{
    int j = blockIdx.x * 256 + threadIdx.x;   // grid 2 x 256 -> 512
    double a = -2.0 * 3.14159265358979323846 * (double)j / (double)NFFT;
    g_twid[j] = make_float2((float)cos(a), (float)sin(a));
}
__global__ void zeroS_kernel() { g_S[blockIdx.x * 1024 + threadIdx.x] = 0.0f; }

__device__ __forceinline__ int brev10(int x) { return (int)(__brev((uint32_t)x) >> 22); }

// forward: Z_c = FFT(q_c + i*k_c) for 8 channels; unpack; accumulate cross-spectrum.
__global__ __launch_bounds__(256)
void fft_fwd_kernel(const float* __restrict__ Q, const float* __restrict__ K)
{
    extern __shared__ __align__(16) float2 Z[];    // 8 * 1024
    __shared__ float2 tw[NFFT/2];
    const int tid = threadIdx.x;
    const int c0  = blockIdx.x * 8;
    const int b   = blockIdx.y;

    for (int i = tid; i < NFFT/2; i += 256) tw[i] = g_twid[i];

    const float* Qb = Q + (size_t)b * L_ * D_ + c0;
    const float* Kb = K + (size_t)b * L_ * D_ + c0;
    for (int i = tid; i < 8 * NFFT; i += 256) {
        const int t = i >> 3, cc = i & 7;
        Z[cc * NFFT + t] = make_float2(Qb[(size_t)t * D_ + cc], Kb[(size_t)t * D_ + cc]);
    }
    __syncthreads();

    #pragma unroll
    for (int st = 0; st < 10; ++st) {
        const int m = 512 >> st;
        for (int i = tid; i < 8 * 512; i += 256) {
            const int col = i >> 9;
            const int bi  = i & 511;
            const int j   = bi & (m - 1);
            const int gg  = bi >> (9 - st);
            const int base = col * NFFT + (gg << (10 - st)) + j;
            float2 u = Z[base], v = Z[base + m];
            float2 w = tw[j << st];
            float2 d = make_float2(u.x - v.x, u.y - v.y);
            Z[base]     = make_float2(u.x + v.x, u.y + v.y);
            Z[base + m] = make_float2(d.x*w.x - d.y*w.y, d.x*w.y + d.y*w.x);
        }
        __syncthreads();
    }

    for (int f = tid; f < NFFT; f += 256) {
        const int p  = brev10(f);
        const int pn = brev10((NFFT - f) & (NFFT - 1));
        float sx = 0.f, sy = 0.f;
        #pragma unroll
        for (int cc = 0; cc < 8; cc++) {
            float2 z1 = Z[cc * NFFT + p];
            float2 z2 = Z[cc * NFFT + pn];
            float Qx = 0.5f * (z1.x + z2.x), Qy = 0.5f * (z1.y - z2.y);
            float wx = z1.x - z2.x,          wy = z1.y + z2.y;
            float Kx = 0.5f * wy,            Ky = -0.5f * wx;
            sx += Qx * Kx + Qy * Ky;
            sy += Qy * Kx - Qx * Ky;
        }
        atomicAdd(&g_S[(b * NFFT + f) * 2    ], sx);
        atomicAdd(&g_S[(b * NFFT + f) * 2 + 1], sy);
    }
}

// inverse: corr[b,tau] = (1/(N*D)) * sum_f S[f] e^{+2pi i f tau/N}
__global__ __launch_bounds__(256)
void fft_inv_kernel(float* __restrict__ corr)
{
    __shared__ float2 Zs[NFFT];
    __shared__ float2 tw[NFFT/2];
    const int tid = threadIdx.x;
    const int b   = blockIdx.x;
    for (int i = tid; i < NFFT/2; i += 256) tw[i] = g_twid[i];
    for (int i = tid; i < NFFT; i += 256)
        Zs[i] = make_float2(g_S[(b * NFFT + i) * 2], g_S[(b * NFFT + i) * 2 + 1]);
    __syncthreads();

    #pragma unroll
    for (int st = 0; st < 10; ++st) {
        const int m = 512 >> st;
        for (int bi = tid; bi < 512; bi += 256) {
            const int j  = bi & (m - 1);
            const int gg = bi >> (9 - st);
            const int base = (gg << (10 - st)) + j;
            float2 u = Zs[base], v = Zs[base + m];
            float2 w = tw[j << st];
            float2 d = make_float2(u.x - v.x, u.y - v.y);
            Zs[base]     = make_float2(u.x + v.x, u.y + v.y);
            Zs[base + m] = make_float2(d.x*w.x + d.y*w.y, d.y*w.x - d.x*w.y);
        }
        __syncthreads();
    }
    const float scale = 1.0f / ((float)NFFT * (float)D_);
    for (int p = tid; p < NFFT; p += 256)
        corr[b * L_ + brev10(p)] = Zs[p].x * scale;
}

// ---------------- top-13 + softmax, one block per batch
__global__ void topk_softmax_kernel(const float* __restrict__ corr,
                                    int* __restrict__ delays, float* __restrict__ w)
{
    const int b   = blockIdx.x;
    const int tid = threadIdx.x;     // 256 threads
    __shared__ float vals[L_];
    __shared__ float rv[256];
    __shared__ int   ri[256];
    __shared__ float topv[TOPK_];
    __shared__ int   topi[TOPK_];

    for (int i = tid; i < L_; i += 256) vals[i] = corr[b * L_ + i];
    __syncthreads();

    for (int sel = 0; sel < TOPK_; sel++) {
        float bv = -FLT_MAX;
        int   bi = 1 << 30;
        for (int i = tid; i < L_; i += 256) {
            float v = vals[i];
            if (v > bv || (v == bv && i < bi)) { bv = v; bi = i; }
        }
        rv[tid] = bv; ri[tid] = bi;
        __syncthreads();
        for (int s = 128; s > 0; s >>= 1) {
            if (tid < s) {
                if (rv[tid+s] > rv[tid] || (rv[tid+s] == rv[tid] && ri[tid+s] < ri[tid])) {
                    rv[tid] = rv[tid+s]; ri[tid] = ri[tid+s];
                }
            }
            __syncthreads();
        }
        if (tid == 0) {
            topv[sel] = rv[0];
            topi[sel] = ri[0];
            vals[ri[0]] = -FLT_MAX;
        }
        __syncthreads();
    }

    if (tid == 0) {
        float mx = topv[0];
        float e[TOPK_], se = 0.0f;
        #pragma unroll
        for (int i = 0; i < TOPK_; i++) { e[i] = expf(topv[i] - mx); se += e[i]; }
        float inv = 1.0f / se;
        #pragma unroll
        for (int i = 0; i < TOPK_; i++) {
            w[b*TOPK_ + i]      = e[i] * inv;
            delays[b*TOPK_ + i] = topi[i];
        }
    }
}

// ------- aggregation: agg[b,t,:] = sum_i w_i * V[b,(t+d_i)%L,:], fp16 split out
__global__ void aggregate_kernel(const float* __restrict__ V,
                                 const int* __restrict__ delays,
                                 const float* __restrict__ w,
                                 __half* __restrict__ Oh,
                                 __half* __restrict__ Om)
{
    const int t = blockIdx.x;
    const int b = blockIdx.y;
    const int c = threadIdx.x;   // 128 threads -> float4 over D=512
    __shared__ int   sd[TOPK_];
    __shared__ float sw[TOPK_];
    if (c < TOPK_) { sd[c] = delays[b*TOPK_ + c]; sw[c] = w[b*TOPK_ + c]; }
    __syncthreads();

    const float4* V4 = (const float4*)V;
    float4 acc = make_float4(0.f, 0.f, 0.f, 0.f);
    #pragma unroll
    for (int i = 0; i < TOPK_; i++) {
        int row = (t + sd[i]) & (L_ - 1);
        float4 vv = V4[((size_t)(b * L_ + row) * (D_/4)) + c];
        float wi = sw[i];
        acc.x = fmaf(wi, vv.x, acc.x);
        acc.y = fmaf(wi, vv.y, acc.y);
        acc.z = fmaf(wi, vv.z, acc.z);
        acc.w = fmaf(wi, vv.w, acc.w);
    }
    const size_t e = ((size_t)(b * L_ + t) * (D_/4) + c) * 4;
    split2_store(make_float2(acc.x, acc.y), Oh, Om, e);
    split2_store(make_float2(acc.z, acc.w), Oh, Om, e + 2);
}

// ---- season = X - moving_average(X,25) via per-thread sliding window ----------
__global__ void movavg_kernel(const float* __restrict__ X, float* __restrict__ OutF,
                              __half* __restrict__ OutH, __half* __restrict__ OutM)
{
    const int seg = blockIdx.x;
    const int b   = blockIdx.y;
    const int c   = threadIdx.x;
    const float4* Xb = (const float4*)X + (size_t)b * L_ * 128;
    const int t0 = seg * 64;

    float sx = 0.f, sy = 0.f, sz = 0.f, sw = 0.f;
    const int lo0 = max(t0 - 12, 0), hi0 = min(t0 + 12, L_ - 1);
    for (int ss = lo0; ss <= hi0; ++ss) {
        float4 v = Xb[(size_t)ss * 128 + c];
        sx += v.x; sy += v.y; sz += v.z; sw += v.w;
    }
    for (int t = t0; t < t0 + 64; ++t) {
        const int lo = max(t - 12, 0), hi = min(t + 12, L_ - 1);
        const float inv = 1.0f / (float)(hi - lo + 1);
        float4 xv = Xb[(size_t)t * 128 + c];
        float4 o;
        o.x = xv.x - sx * inv;
        o.y = xv.y - sy * inv;
        o.z = xv.z - sz * inv;
        o.w = xv.w - sw * inv;
        const size_t oi = (size_t)(b * L_ + t) * 128 + c;
        ((float4*)OutF)[oi] = o;
        if (OutH) {
            split2_store(make_float2(o.x, o.y), OutH, OutM, oi * 4);
            split2_store(make_float2(o.z, o.w), OutH, OutM, oi * 4 + 2);
        }
        if (t + 13 <= L_ - 1) {
            float4 v = Xb[(size_t)(t + 13) * 128 + c];
            sx += v.x; sy += v.y; sz += v.z; sw += v.w;
        }
        if (t - 12 >= 0) {
            float4 v = Xb[(size_t)(t - 12) * 128 + c];
            sx -= v.x; sy -= v.y; sz -= v.z; sw -= v.w;
        }
    }
}

// ---------------- host launch ----------------
extern "C" void kernel_launch(void* const* d_in, const int* in_sizes, int n_in,
                              void* d_out, int out_size)
{
    const float* x  = (const float*)d_in[0];
    const float* Wq = (const float*)d_in[1];
    const float* bq = (const float*)d_in[2];
    const float* Wk = (const float*)d_in[3];
    const float* bk = (const float*)d_in[4];
    const float* Wv = (const float*)d_in[5];
    const float* bv = (const float*)d_in[6];
    const float* Wo = (const float*)d_in[7];
    const float* bo = (const float*)d_in[8];
    const float* Wd = (const float*)d_in[9];
    const float* bd = (const float*)d_in[10];
    float* out = (float*)d_out;

    float *v, *qf, *kf, *x1, *s1, *x2, *corr, *w;
    int* dl;
    __half *xh, *xm, *ah, *am, *sh, *sm, *wth;
    cudaGetSymbolAddress((void**)&v,    g_v);
    cudaGetSymbolAddress((void**)&qf,   g_qf);
    cudaGetSymbolAddress((void**)&kf,   g_kf);
    cudaGetSymbolAddress((void**)&x1,   g_x1);
    cudaGetSymbolAddress((void**)&s1,   g_s1);
    cudaGetSymbolAddress((void**)&x2,   g_x2);
    cudaGetSymbolAddress((void**)&corr, g_corr);
    cudaGetSymbolAddress((void**)&dl,   g_delay);
    cudaGetSymbolAddress((void**)&w,    g_w);
    cudaGetSymbolAddress((void**)&xh,   g_xh);  cudaGetSymbolAddress((void**)&xm, g_xm);
    cudaGetSymbolAddress((void**)&ah,   g_ah);  cudaGetSymbolAddress((void**)&am, g_am);
    cudaGetSymbolAddress((void**)&sh,   g_sh);  cudaGetSymbolAddress((void**)&sm, g_sm);
    cudaGetSymbolAddress((void**)&wth,  g_wth);

    cudaFuncSetAttribute(gemm_hf, cudaFuncAttributeMaxDynamicSharedMemorySize, SMEM_MMA);
    cudaFuncSetAttribute(fft_fwd_kernel, cudaFuncAttributeMaxDynamicSharedMemorySize, 8*NFFT*8);

    // input splits + twiddles
    xsplit_kernel<<<NEL_/4/256, 256>>>(x, xh, xm);
    dim3 tT(32, 8), gT(16, 16, 5);
    wtsplit_kernel<<<gT, tT>>>(Wq, Wk, Wv, Wo, Wd, wth);
    twiddle_kernel<<<2, 256>>>();

    dim3 t256(256);
    dim3 gdense(D_/128, (B_*L_)/128);     // (4, 256)

    // projections (fp32 outputs)
    gemm_hf<<<gdense, t256, SMEM_MMA>>>(xh, xm, wth + 0*D_*D_, bq, nullptr, qf);
    gemm_hf<<<gdense, t256, SMEM_MMA>>>(xh, xm, wth + 1*D_*D_, bk, nullptr, kf);
    gemm_hf<<<gdense, t256, SMEM_MMA>>>(xh, xm, wth + 2*D_*D_, bv, nullptr, v);

    // FFT autocorrelation -> corr
    zeroS_kernel<<<B_*2, 1024>>>();
    dim3 gfft(D_/8, B_);
    fft_fwd_kernel<<<gfft, 256, 8*NFFT*8>>>(qf, kf);
    fft_inv_kernel<<<B_, 256>>>(corr);

    // top-13 + softmax per batch
    topk_softmax_kernel<<<B_, 256>>>(corr, dl, w);

    // delay aggregation of V -> fp16 split agg
    dim3 gld(L_, B_);
    aggregate_kernel<<<gld, 128>>>(v, dl, w, ah, am);

    // x1 = agg @ Wo + bo + x
    gemm_hf<<<gdense, t256, SMEM_MMA>>>(ah, am, wth + 3*D_*D_, bo, x, x1);

    // s1 = x1 - movavg(x1), plus fp16 split s1
    dim3 gma(16, B_);
    movavg_kernel<<<gma, 128>>>(x1, s1, sh, sm);

    // x2 = s1 @ Wd + bd + s1
    gemm_hf<<<gdense, t256, SMEM_MMA>>>(sh, sm, wth + 4*D_*D_, bd, s1, x2);

    // out = x2 - movavg(x2)
    movavg_kernel<<<gma, 128>>>(x2, out, nullptr, nullptr);
}

// round 12
// speedup vs baseline: 2.5471x; 1.0014x over previous
#include <cuda_runtime.h>
#include <cuda_fp16.h>
#include <math.h>
#include <float.h>
#include <stdint.h>

#define B_    32
#define L_    1024
#define D_    512
#define TOPK_ 13
#define NEL_  (B_*L_*D_)
#define NFFT  1024

// ---------------- scratch (static device globals; no allocation) ----------------
__device__ float g_v [NEL_];
__device__ float g_qf[NEL_];
__device__ float g_kf[NEL_];
__device__ float g_x1[NEL_];
__device__ float g_s1[NEL_];
__device__ float g_x2[NEL_];
__device__ float g_corr[B_*L_];
__device__ int   g_delay[B_*TOPK_];
__device__ float g_w[B_*TOPK_];
__device__ float g_S[B_*NFFT*2];
__device__ float2 g_twid[NFFT/2];
__device__ __half g_xh[NEL_],  g_xm[NEL_];
__device__ __half g_ah[NEL_],  g_am[NEL_];
__device__ __half g_sh[NEL_],  g_sm[NEL_];
__device__ __half g_wth[5*D_*D_];        // Wq^T,Wk^T,Wv^T,Wo^T,Wd^T (hi only, contiguous)

// ================= portable PTX helpers =================
__device__ __forceinline__ uint32_t smem_to_u32(const void* p) {
    uint32_t a;
    asm("{ .reg .u64 t; cvta.to.shared.u64 t, %1; cvt.u32.u64 %0, t; }" : "=r"(a) : "l"(p));
    return a;
}
#define LDMX4(r0,r1,r2,r3,addr) \
    asm volatile("ldmatrix.sync.aligned.m8n8.x4.shared.b16 {%0,%1,%2,%3}, [%4];" \
        : "=r"(r0), "=r"(r1), "=r"(r2), "=r"(r3) : "r"(addr))
#define MMA16816(c,a,b) \
    asm volatile("mma.sync.aligned.m16n8k16.row.col.f32.f16.f16.f32 " \
        "{%0,%1,%2,%3},{%4,%5,%6,%7},{%8,%9},{%0,%1,%2,%3};" \
        : "+f"((c)[0]), "+f"((c)[1]), "+f"((c)[2]), "+f"((c)[3]) \
        : "r"((a)[0]), "r"((a)[1]), "r"((a)[2]), "r"((a)[3]), "r"((b)[0]), "r"((b)[1]))
#define CP16(dst, src) \
    asm volatile("cp.async.cg.shared.global [%0], [%1], 16;" :: "r"(dst), "l"(src) : "memory")
#define CPCOMMIT() asm volatile("cp.async.commit_group;" ::: "memory")
#define CPWAIT1()  asm volatile("cp.async.wait_group 1;" ::: "memory")
#define CPWAIT0()  asm volatile("cp.async.wait_group 0;" ::: "memory")

__device__ __forceinline__ void split2_store(float2 v, __half* H, __half* M, size_t e) {
    __half2 h = __float22half2_rn(v);
    float2 r = make_float2(v.x - __half2float(h.x), v.y - __half2float(h.y));
    __half2 m = __float22half2_rn(r);
    *(__half2*)(H + e) = h;
    *(__half2*)(M + e) = m;
}

// ========= fp16 2-product MMA GEMM, 3-stage pipeline, fused-output select =====
// A(h/m): [M,512] fp16 NT; B(h): [Nrows,512] fp16 NT (Nrows = 512*nsplit).
// Output/bias selected per n0>>9 (QKV fusion); product = Ah*Bh + Am*Bh.
#define ROWB   80
#define TILEB  (128*ROWB)      // 10240
#define STAGEB (3*TILEB)       // 30720
#define SMEM_MMA (3*STAGEB)    // 92160 (3 stages)

__global__ __launch_bounds__(256, 2)
void gemm_hf(const __half* __restrict__ Ah, const __half* __restrict__ Am,
             const __half* __restrict__ Bh,
             const float* __restrict__ b0, const float* __restrict__ b1,
             const float* __restrict__ b2,
             const float* __restrict__ res,
             float* __restrict__ o0, float* __restrict__ o1, float* __restrict__ o2)
{
    extern __shared__ __align__(128) char smem[];
    const int tid  = threadIdx.x;
    const int wid  = tid >> 5;
    const int lane = tid & 31;
    const int m0 = blockIdx.y * 128;
    const int n0 = blockIdx.x * 128;
    const int nblk  = n0 >> 9;
    const int ncol0 = n0 & 511;
    const float* bias = (nblk == 0) ? b0 : (nblk == 1) ? b1 : b2;
    float* outF       = (nblk == 0) ? o0 : (nblk == 1) ? o1 : o2;
    const uint32_t sb = smem_to_u32(smem);

    const int g  = lane >> 2, tg = lane & 3;
    const int wm = wid >> 1,  wn = wid & 1;

    float acc[2][8][4];
    #pragma unroll
    for (int i = 0; i < 2; i++)
        #pragma unroll
        for (int j = 0; j < 8; j++)
            #pragma unroll
            for (int r = 0; r < 4; r++) acc[i][j][r] = 0.0f;

    const int asel = lane >> 3, ar = lane & 7;
    const int rq = (asel & 1) * 8 + ar;
    const int kq = (asel >> 1) * 8;

    const int crow = tid >> 1;
    const int coff = (tid & 1);
    const __half* Ahp = Ah + (size_t)(m0 + crow) * D_ + coff * 16;
    const __half* Amp = Am + (size_t)(m0 + crow) * D_ + coff * 16;
    const __half* Bhp = Bh + (size_t)(n0 + crow) * D_ + coff * 16;
    const uint32_t drow = (uint32_t)(crow * ROWB + coff * 32);

    auto issue = [&](int c, int s) {
        const uint32_t db = sb + s * STAGEB + drow;
        const size_t go = (size_t)c * 32;
        CP16(db + 0*TILEB,      Ahp + go);
        CP16(db + 0*TILEB + 16, Ahp + go + 8);
        CP16(db + 1*TILEB,      Amp + go);
        CP16(db + 1*TILEB + 16, Amp + go + 8);
        CP16(db + 2*TILEB,      Bhp + go);
        CP16(db + 2*TILEB + 16, Bhp + go + 8);
    };

    issue(0, 0); CPCOMMIT();
    issue(1, 1); CPCOMMIT();

    for (int c = 0; c < 16; ++c) {
        const int s = c % 3;
        if (c < 15) CPWAIT1(); else CPWAIT0();
        __syncthreads();                           // chunk c visible; chunk c-1 fully consumed
        if (c + 2 < 16) { issue(c + 2, (c + 2) % 3); CPCOMMIT(); }

        const uint32_t aHi  = sb + s*STAGEB;
        const uint32_t aMid = aHi + TILEB;
        const uint32_t bHi  = aHi + 2*TILEB;

        #pragma unroll
        for (int kk = 0; kk < 32; kk += 16) {
            uint32_t ah[2][4], am[2][4], bh[8][2];
            #pragma unroll
            for (int mt = 0; mt < 2; mt++) {
                const uint32_t ao = (uint32_t)((wm*32 + mt*16 + rq)*ROWB + (kk + kq)*2);
                LDMX4(ah[mt][0], ah[mt][1], ah[mt][2], ah[mt][3], aHi  + ao);
                LDMX4(am[mt][0], am[mt][1], am[mt][2], am[mt][3], aMid + ao);
            }
            #pragma unroll
            for (int np = 0; np < 4; np++) {
                uint32_t r0, r1, r2, r3;
                const uint32_t bo = (uint32_t)((wn*64 + np*16 + rq)*ROWB + (kk + kq)*2);
                LDMX4(r0, r1, r2, r3, bHi + bo);
                bh[2*np][0]   = r0; bh[2*np][1]   = r2;
                bh[2*np+1][0] = r1; bh[2*np+1][1] = r3;
            }
            #pragma unroll
            for (int nt = 0; nt < 8; nt++)
                #pragma unroll
                for (int mt = 0; mt < 2; mt++)
                    MMA16816(acc[mt][nt], ah[mt], bh[nt]);
            #pragma unroll
            for (int nt = 0; nt < 8; nt++)
                #pragma unroll
                for (int mt = 0; mt < 2; mt++)
                    MMA16816(acc[mt][nt], am[mt], bh[nt]);
        }
    }

    // ---- epilogue ----
    #pragma unroll
    for (int mt = 0; mt < 2; mt++) {
        const int row0 = m0 + wm*32 + mt*16 + g;
        #pragma unroll
        for (int nt = 0; nt < 8; nt++) {
            const int col = ncol0 + wn*64 + nt*8 + tg*2;
            float bb0 = 0.f, bb1 = 0.f;
            if (bias) { bb0 = bias[col]; bb1 = bias[col + 1]; }
            float2 v0 = make_float2(acc[mt][nt][0] + bb0, acc[mt][nt][1] + bb1);
            float2 v1 = make_float2(acc[mt][nt][2] + bb0, acc[mt][nt][3] + bb1);
            const size_t i0 = (size_t)row0 * D_ + col;
            const size_t i1 = (size_t)(row0 + 8) * D_ + col;
            if (res) {
                float2 r0 = *(const float2*)&res[i0];
                float2 r1 = *(const float2*)&res[i1];
                v0.x += r0.x; v0.y += r0.y;
                v1.x += r1.x; v1.y += r1.y;
            }
            *(float2*)&outF[i0] = v0;
            *(float2*)&outF[i1] = v1;
        }
    }
}

// ---------------- x -> hi/mid fp16 split ----------------
__global__ void xsplit_kernel(const float* __restrict__ X,
                              __half* __restrict__ H, __half* __restrict__ M)
{
    const size_t i = (size_t)blockIdx.x * blockDim.x + threadIdx.x;
    float4 v = ((const float4*)X)[i];
    split2_store(make_float2(v.x, v.y), H, M, i*4);
    split2_store(make_float2(v.z, v.w), H, M, i*4 + 2);
}

// ------- merged weight transpose + fp16 hi (grid.z selects weight) -------------
__global__ void wtsplit_kernel(const float* __restrict__ W0, const float* __restrict__ W1,
                               const float* __restrict__ W2, const float* __restrict__ W3,
                               const float* __restrict__ W4,
                               __half* __restrict__ oh)
{
    const int z = blockIdx.z;
    const float* in = (z == 0) ? W0 : (z == 1) ? W1 : (z == 2) ? W2 : (z == 3) ? W3 : W4;
    oh += (size_t)z * D_ * D_;
    __shared__ float t[32][33];
    const int bx = blockIdx.x * 32, by = blockIdx.y * 32;
    const int tx = threadIdx.x, ty = threadIdx.y;
    #pragma unroll
    for (int r = 0; r < 32; r += 8)
        t[ty + r][tx] = in[(size_t)(by + ty + r) * D_ + bx + tx];
    __syncthreads();
    #pragma unroll
    for (int r = 0; r < 32; r += 8) {
        float v = t[tx][ty + r];
        oh[(size_t)(bx + ty + r) * D_ + by + tx] = __float2half_rn(v);
    }
}

// ---------------- FFT machinery ----------------
__global__ void twiddle_kernel()
{
    int j = blockIdx.x * 256 + threadIdx.x;
    double a = -2.0 * 3.14159265358979323846 * (double)j / (double)NFFT;
    g_twid[j] = make_float2((float)cos(a), (float)sin(a));
}
__global__ void zeroS_kernel() { g_S[blockIdx.x * 1024 + threadIdx.x] = 0.0f; }

__device__ __forceinline__ int brev10(int x) { return (int)(__brev((uint32_t)x) >> 22); }
__device__ __forceinline__ float2 cadd(float2 a, float2 b) { return make_float2(a.x+b.x, a.y+b.y); }
__device__ __forceinline__ float2 csub(float2 a, float2 b) { return make_float2(a.x-b.x, a.y-b.y); }
__device__ __forceinline__ float2 cmul(float2 a, float2 w) {
    return make_float2(a.x*w.x - a.y*w.y, a.x*w.y + a.y*w.x);
}
__device__ __forceinline__ float2 cmulc(float2 a, float2 w) {   // a * conj(w)
    return make_float2(a.x*w.x + a.y*w.y, a.y*w.x - a.x*w.y);
}

// forward: Z_c = FFT(q_c + i*k_c), 8 channels/block. Fused-pair radix-2 (5 smem passes).
__global__ __launch_bounds__(256)
void fft_fwd_kernel(const float* __restrict__ Q, const float* __restrict__ K)
{
    extern __shared__ __align__(16) float2 Z[];    // 8 * 1024
    __shared__ float2 tw[NFFT/2];
    const int tid = threadIdx.x;
    const int c0  = blockIdx.x * 8;
    const int b   = blockIdx.y;

    for (int i = tid; i < NFFT/2; i += 256) tw[i] = g_twid[i];

    const float* Qb = Q + (size_t)b * L_ * D_ + c0;
    const float* Kb = K + (size_t)b * L_ * D_ + c0;
    for (int i = tid; i < 8 * NFFT; i += 256) {
        const int t = i >> 3, cc = i & 7;
        Z[cc * NFFT + t] = make_float2(Qb[(size_t)t * D_ + cc], Kb[(size_t)t * D_ + cc]);
    }
    __syncthreads();

    // two radix-2 stages fused per smem pass (identical math/permutation)
    #pragma unroll
    for (int st = 0; st < 10; st += 2) {
        const int m = 512 >> st;       // stage-st pair separation
        const int h = m >> 1;          // stage-(st+1) separation
        for (int i = tid; i < 8 * 256; i += 256) {
            const int col = i >> 8;
            const int gi  = i & 255;
            const int j   = gi & (h - 1);
            const int gg  = gi >> (8 - st);
            const int base = col * NFFT + (gg << (10 - st)) + j;
            float2 e0 = Z[base], e1 = Z[base + h], e2 = Z[base + m], e3 = Z[base + m + h];
            float2 wa = tw[j << st];
            float2 wb = tw[(j + h) << st];
            float2 wc = tw[j << (st + 1)];
            float2 u0 = cadd(e0, e2), v0 = cmul(csub(e0, e2), wa);
            float2 u1 = cadd(e1, e3), v1 = cmul(csub(e1, e3), wb);
            Z[base]         = cadd(u0, u1);
            Z[base + h]     = cmul(csub(u0, u1), wc);
            Z[base + m]     = cadd(v0, v1);
            Z[base + m + h] = cmul(csub(v0, v1), wc);
        }
        __syncthreads();
    }

    for (int f = tid; f < NFFT; f += 256) {
        const int p  = brev10(f);
        const int pn = brev10((NFFT - f) & (NFFT - 1));
        float sx = 0.f, sy = 0.f;
        #pragma unroll
        for (int cc = 0; cc < 8; cc++) {
            float2 z1 = Z[cc * NFFT + p];
            float2 z2 = Z[cc * NFFT + pn];
            float Qx = 0.5f * (z1.x + z2.x), Qy = 0.5f * (z1.y - z2.y);
            float wx = z1.x - z2.x,          wy = z1.y + z2.y;
            float Kx = 0.5f * wy,            Ky = -0.5f * wx;
            sx += Qx * Kx + Qy * Ky;
            sy += Qy * Kx - Qx * Ky;
        }
        atomicAdd(&g_S[(b * NFFT + f) * 2    ], sx);
        atomicAdd(&g_S[(b * NFFT + f) * 2 + 1], sy);
    }
}

// inverse: corr[b,tau] = (1/(N*D)) * sum_f S[f] e^{+2pi i f tau/N}; fused pairs.
__global__ __launch_bounds__(256)
void fft_inv_kernel(float* __restrict__ corr)
{
    __shared__ float2 Zs[NFFT];
    __shared__ float2 tw[NFFT/2];
    const int tid = threadIdx.x;
    const int b   = blockIdx.x;
    for (int i = tid; i < NFFT/2; i += 256) tw[i] = g_twid[i];
    for (int i = tid; i < NFFT; i += 256)
        Zs[i] = make_float2(g_S[(b * NFFT + i) * 2], g_S[(b * NFFT + i) * 2 + 1]);
    __syncthreads();

    #pragma unroll
    for (int st = 0; st < 10; st += 2) {
        const int m = 512 >> st;
        const int h = m >> 1;
        for (int gi = tid; gi < 256; gi += 256) {
            const int j  = gi & (h - 1);
            const int gg = gi >> (8 - st);
            const int base = (gg << (10 - st)) + j;
            float2 e0 = Zs[base], e1 = Zs[base + h], e2 = Zs[base + m], e3 = Zs[base + m + h];
            float2 wa = tw[j << st];
            float2 wb = tw[(j + h) << st];
            float2 wc = tw[j << (st + 1)];
            float2 u0 = cadd(e0, e2), v0 = cmulc(csub(e0, e2), wa);
            float2 u1 = cadd(e1, e3), v1 = cmulc(csub(e1, e3), wb);
            Zs[base]         = cadd(u0, u1);
            Zs[base + h]     = cmulc(csub(u0, u1), wc);
            Zs[base + m]     = cadd(v0, v1);
            Zs[base + m + h] = cmulc(csub(v0, v1), wc);
        }
        __syncthreads();
    }
    const float scale = 1.0f / ((float)NFFT * (float)D_);
    for (int p = tid; p < NFFT; p += 256)
        corr[b * L_ + brev10(p)] = Zs[p].x * scale;
}

// ---------------- top-13 + softmax, one block per batch
__global__ void topk_softmax_kernel(const float* __restrict__ corr,
                                    int* __restrict__ delays, float* __restrict__ w)
{
    const int b   = blockIdx.x;
    const int tid = threadIdx.x;
    __shared__ float vals[L_];
    __shared__ float rv[256];
    __shared__ int   ri[256];
    __shared__ float topv[TOPK_];
    __shared__ int   topi[TOPK_];

    for (int i = tid; i < L_; i += 256) vals[i] = corr[b * L_ + i];
    __syncthreads();

    for (int sel = 0; sel < TOPK_; sel++) {
        float bv = -FLT_MAX;
        int   bi = 1 << 30;
        for (int i = tid; i < L_; i += 256) {
            float v = vals[i];
            if (v > bv || (v == bv && i < bi)) { bv = v; bi = i; }
        }
        rv[tid] = bv; ri[tid] = bi;
        __syncthreads();
        for (int s = 128; s > 0; s >>= 1) {
            if (tid < s) {
                if (rv[tid+s] > rv[tid] || (rv[tid+s] == rv[tid] && ri[tid+s] < ri[tid])) {
                    rv[tid] = rv[tid+s]; ri[tid] = ri[tid+s];
                }
            }
            __syncthreads();
        }
        if (tid == 0) {
            topv[sel] = rv[0];
            topi[sel] = ri[0];
            vals[ri[0]] = -FLT_MAX;
        }
        __syncthreads();
    }

    if (tid == 0) {
        float mx = topv[0];
        float e[TOPK_], se = 0.0f;
        #pragma unroll
        for (int i = 0; i < TOPK_; i++) { e[i] = expf(topv[i] - mx); se += e[i]; }
        float inv = 1.0f / se;
        #pragma unroll
        for (int i = 0; i < TOPK_; i++) {
            w[b*TOPK_ + i]      = e[i] * inv;
            delays[b*TOPK_ + i] = topi[i];
        }
    }
}

// ------- aggregation: agg[b,t,:] = sum_i w_i * V[b,(t+d_i)%L,:], fp16 split out
__global__ void aggregate_kernel(const float* __restrict__ V,
                                 const int* __restrict__ delays,
                                 const float* __restrict__ w,
                                 __half* __restrict__ Oh,
                                 __half* __restrict__ Om)
{
    const int t = blockIdx.x;
    const int b = blockIdx.y;
    const int c = threadIdx.x;
    __shared__ int   sd[TOPK_];
    __shared__ float sw[TOPK_];
    if (c < TOPK_) { sd[c] = delays[b*TOPK_ + c]; sw[c] = w[b*TOPK_ + c]; }
    __syncthreads();

    const float4* V4 = (const float4*)V;
    float4 acc = make_float4(0.f, 0.f, 0.f, 0.f);
    #pragma unroll
    for (int i = 0; i < TOPK_; i++) {
        int row = (t + sd[i]) & (L_ - 1);
        float4 vv = V4[((size_t)(b * L_ + row) * (D_/4)) + c];
        float wi = sw[i];
        acc.x = fmaf(wi, vv.x, acc.x);
        acc.y = fmaf(wi, vv.y, acc.y);
        acc.z = fmaf(wi, vv.z, acc.z);
        acc.w = fmaf(wi, vv.w, acc.w);
    }
    const size_t e = ((size_t)(b * L_ + t) * (D_/4) + c) * 4;
    split2_store(make_float2(acc.x, acc.y), Oh, Om, e);
    split2_store(make_float2(acc.z, acc.w), Oh, Om, e + 2);
}

// ---- season = X - moving_average(X,25) via per-thread sliding window ----------
__global__ void movavg_kernel(const float* __restrict__ X, float* __restrict__ OutF,
                              __half* __restrict__ OutH, __half* __restrict__ OutM)
{
    const int seg = blockIdx.x;
    const int b   = blockIdx.y;
    const int c   = threadIdx.x;
    const float4* Xb = (const float4*)X + (size_t)b * L_ * 128;
    const int t0 = seg * 64;

    float sx = 0.f, sy = 0.f, sz = 0.f, sw = 0.f;
    const int lo0 = max(t0 - 12, 0), hi0 = min(t0 + 12, L_ - 1);
    for (int ss = lo0; ss <= hi0; ++ss) {
        float4 v = Xb[(size_t)ss * 128 + c];
        sx += v.x; sy += v.y; sz += v.z; sw += v.w;
    }
    for (int t = t0; t < t0 + 64; ++t) {
        const int lo = max(t - 12, 0), hi = min(t + 12, L_ - 1);
        const float inv = 1.0f / (float)(hi - lo + 1);
        float4 xv = Xb[(size_t)t * 128 + c];
        float4 o;
        o.x = xv.x - sx * inv;
        o.y = xv.y - sy * inv;
        o.z = xv.z - sz * inv;
        o.w = xv.w - sw * inv;
        const size_t oi = (size_t)(b * L_ + t) * 128 + c;
        ((float4*)OutF)[oi] = o;
        if (OutH) {
            split2_store(make_float2(o.x, o.y), OutH, OutM, oi * 4);
            split2_store(make_float2(o.z, o.w), OutH, OutM, oi * 4 + 2);
        }
        if (t + 13 <= L_ - 1) {
            float4 v = Xb[(size_t)(t + 13) * 128 + c];
            sx += v.x; sy += v.y; sz += v.z; sw += v.w;
        }
        if (t - 12 >= 0) {
            float4 v = Xb[(size_t)(t - 12) * 128 + c];
            sx -= v.x; sy -= v.y; sz -= v.z; sw -= v.w;
        }
    }
}

// ---------------- host launch ----------------
extern "C" void kernel_launch(void* const* d_in, const int* in_sizes, int n_in,
                              void* d_out, int out_size)
{
    const float* x  = (const float*)d_in[0];
    const float* Wq = (const float*)d_in[1];
    const float* bq = (const float*)d_in[2];
    const float* Wk = (const float*)d_in[3];
    const float* bk = (const float*)d_in[4];
    const float* Wv = (const float*)d_in[5];
    const float* bv = (const float*)d_in[6];
    const float* Wo = (const float*)d_in[7];
    const float* bo = (const float*)d_in[8];
    const float* Wd = (const float*)d_in[9];
    const float* bd = (const float*)d_in[10];
    float* out = (float*)d_out;

    float *v, *qf, *kf, *x1, *s1, *x2, *corr, *w;
    int* dl;
    __half *xh, *xm, *ah, *am, *sh, *sm, *wth;
    cudaGetSymbolAddress((void**)&v,    g_v);
    cudaGetSymbolAddress((void**)&qf,   g_qf);
    cudaGetSymbolAddress((void**)&kf,   g_kf);
    cudaGetSymbolAddress((void**)&x1,   g_x1);
    cudaGetSymbolAddress((void**)&s1,   g_s1);
    cudaGetSymbolAddress((void**)&x2,   g_x2);
    cudaGetSymbolAddress((void**)&corr, g_corr);
    cudaGetSymbolAddress((void**)&dl,   g_delay);
    cudaGetSymbolAddress((void**)&w,    g_w);
    cudaGetSymbolAddress((void**)&xh,   g_xh);  cudaGetSymbolAddress((void**)&xm, g_xm);
    cudaGetSymbolAddress((void**)&ah,   g_ah);  cudaGetSymbolAddress((void**)&am, g_am);
    cudaGetSymbolAddress((void**)&sh,   g_sh);  cudaGetSymbolAddress((void**)&sm, g_sm);
    cudaGetSymbolAddress((void**)&wth,  g_wth);

    cudaFuncSetAttribute(gemm_hf, cudaFuncAttributeMaxDynamicSharedMemorySize, SMEM_MMA);
    cudaFuncSetAttribute(fft_fwd_kernel, cudaFuncAttributeMaxDynamicSharedMemorySize, 8*NFFT*8);

    // input splits + twiddles
    xsplit_kernel<<<NEL_/4/256, 256>>>(x, xh, xm);
    dim3 tT(32, 8), gT(16, 16, 5);
    wtsplit_kernel<<<gT, tT>>>(Wq, Wk, Wv, Wo, Wd, wth);
    twiddle_kernel<<<2, 256>>>();

    dim3 t256(256);
    dim3 gQKV(3*D_/128, (B_*L_)/128);     // (12, 256) fused QKV
    dim3 gdense(D_/128, (B_*L_)/128);     // (4, 256)

    // fused Q/K/V projection: one GEMM over concatenated weights
    gemm_hf<<<gQKV, t256, SMEM_MMA>>>(xh, xm, wth, bq, bk, bv, nullptr, qf, kf, v);

    // FFT autocorrelation -> corr
    zeroS_kernel<<<B_*2, 1024>>>();
    dim3 gfft(D_/8, B_);
    fft_fwd_kernel<<<gfft, 256, 8*NFFT*8>>>(qf, kf);
    fft_inv_kernel<<<B_, 256>>>(corr);

    // top-13 + softmax per batch
    topk_softmax_kernel<<<B_, 256>>>(corr, dl, w);

    // delay aggregation of V -> fp16 split agg
    dim3 gld(L_, B_);
    aggregate_kernel<<<gld, 128>>>(v, dl, w, ah, am);

    // x1 = agg @ Wo + bo + x
    gemm_hf<<<gdense, t256, SMEM_MMA>>>(ah, am, wth + 3*D_*D_,
                                        bo, bo, bo, x, x1, x1, x1);

    // s1 = x1 - movavg(x1), plus fp16 split s1
    dim3 gma(16, B_);
    movavg_kernel<<<gma, 128>>>(x1, s1, sh, sm);

    // x2 = s1 @ Wd + bd + s1
    gemm_hf<<<gdense, t256, SMEM_MMA>>>(sh, sm, wth + 4*D_*D_,
                                        bd, bd, bd, s1, x2, x2, x2);

    // out = x2 - movavg(x2)
    movavg_kernel<<<gma, 128>>>(x2, out, nullptr, nullptr);
}

// round 14
// speedup vs baseline: 2.6572x; 1.0432x over previous
#include <cuda_runtime.h>
#include <cuda_fp16.h>
#include <math.h>
#include <float.h>
#include <stdint.h>

#define B_    32
#define L_    1024
#define D_    512
#define TOPK_ 13
#define NEL_  (B_*L_*D_)
#define NFFT  1024

// ---------------- scratch (static device globals; no allocation) ----------------
__device__ float g_v [NEL_];
__device__ float g_qT[NEL_];             // channel-major: [B][D][L]
__device__ float g_kT[NEL_];
__device__ float g_x1[NEL_];
__device__ float g_s1[NEL_];
__device__ float g_x2[NEL_];
__device__ int   g_delay[B_*TOPK_];
__device__ float g_w[B_*TOPK_];
__device__ float g_S[B_*NFFT*2];
__device__ float2 g_twid[NFFT/2];
__device__ __half g_xh[NEL_],  g_xm[NEL_];
__device__ __half g_ah[NEL_],  g_am[NEL_];
__device__ __half g_sh[NEL_],  g_sm[NEL_];
__device__ __half g_wth[5*D_*D_];        // Wq^T,Wk^T,Wv^T,Wo^T,Wd^T (hi only)

// ================= portable PTX helpers =================
__device__ __forceinline__ uint32_t smem_to_u32(const void* p) {
    uint32_t a;
    asm("{ .reg .u64 t; cvta.to.shared.u64 t, %1; cvt.u32.u64 %0, t; }" : "=r"(a) : "l"(p));
    return a;
}
#define LDMX4(r0,r1,r2,r3,addr) \
    asm volatile("ldmatrix.sync.aligned.m8n8.x4.shared.b16 {%0,%1,%2,%3}, [%4];" \
        : "=r"(r0), "=r"(r1), "=r"(r2), "=r"(r3) : "r"(addr))
#define MMA16816(c,a,b) \
    asm volatile("mma.sync.aligned.m16n8k16.row.col.f32.f16.f16.f32 " \
        "{%0,%1,%2,%3},{%4,%5,%6,%7},{%8,%9},{%0,%1,%2,%3};" \
        : "+f"((c)[0]), "+f"((c)[1]), "+f"((c)[2]), "+f"((c)[3]) \
        : "r"((a)[0]), "r"((a)[1]), "r"((a)[2]), "r"((a)[3]), "r"((b)[0]), "r"((b)[1]))
#define CP16(dst, src) \
    asm volatile("cp.async.cg.shared.global [%0], [%1], 16;" :: "r"(dst), "l"(src) : "memory")
#define CPCOMMIT() asm volatile("cp.async.commit_group;" ::: "memory")
#define CPWAIT1()  asm volatile("cp.async.wait_group 1;" ::: "memory")
#define CPWAIT0()  asm volatile("cp.async.wait_group 0;" ::: "memory")

__device__ __forceinline__ void split2_store(float2 v, __half* H, __half* M, size_t e) {
    __half2 h = __float22half2_rn(v);
    float2 r = make_float2(v.x - __half2float(h.x), v.y - __half2float(h.y));
    __half2 m = __float22half2_rn(r);
    *(__half2*)(H + e) = h;
    *(__half2*)(M + e) = m;
}

// ========= fp16 2-product MMA GEMM, 3-stage pipeline ==========================
// A(h/m): [M,512] fp16 NT; B(h): [Nrows,512] fp16 NT. Product = Ah*Bh + Am*Bh.
// qkT: outputs for nblk<2 are written channel-major [B][D][L] via smem transpose.
#define ROWB   80
#define TILEB  (128*ROWB)      // 10240
#define STAGEB (3*TILEB)       // 30720
#define SMEM_MMA (3*STAGEB)    // 92160 (>= 128*132*4 = 67584 transpose staging)

__global__ __launch_bounds__(256, 2)
void gemm_hf(const __half* __restrict__ Ah, const __half* __restrict__ Am,
             const __half* __restrict__ Bh,
             const float* __restrict__ b0, const float* __restrict__ b1,
             const float* __restrict__ b2,
             const float* __restrict__ res,
             float* __restrict__ o0, float* __restrict__ o1, float* __restrict__ o2,
             int qkT)
{
    extern __shared__ __align__(128) char smem[];
    const int tid  = threadIdx.x;
    const int wid  = tid >> 5;
    const int lane = tid & 31;
    const int m0 = blockIdx.y * 128;
    const int n0 = blockIdx.x * 128;
    const int nblk  = n0 >> 9;
    const int ncol0 = n0 & 511;
    const float* bias = (nblk == 0) ? b0 : (nblk == 1) ? b1 : b2;
    float* outF       = (nblk == 0) ? o0 : (nblk == 1) ? o1 : o2;
    const uint32_t sb = smem_to_u32(smem);

    const int g  = lane >> 2, tg = lane & 3;
    const int wm = wid >> 1,  wn = wid & 1;

    float acc[2][8][4];
    #pragma unroll
    for (int i = 0; i < 2; i++)
        #pragma unroll
        for (int j = 0; j < 8; j++)
            #pragma unroll
            for (int r = 0; r < 4; r++) acc[i][j][r] = 0.0f;

    const int asel = lane >> 3, ar = lane & 7;
    const int rq = (asel & 1) * 8 + ar;
    const int kq = (asel >> 1) * 8;
    const uint32_t aoA = (uint32_t)((wm*32 + rq)*ROWB + kq*2);
    const uint32_t aoB = (uint32_t)((wn*64 + rq)*ROWB + kq*2);

    const int crow = tid >> 1;
    const int coff = (tid & 1);
    const __half* Ahp = Ah + (size_t)(m0 + crow) * D_ + coff * 16;
    const __half* Amp = Am + (size_t)(m0 + crow) * D_ + coff * 16;
    const __half* Bhp = Bh + (size_t)(n0 + crow) * D_ + coff * 16;
    const uint32_t drow = (uint32_t)(crow * ROWB + coff * 32);

    auto issue = [&](int c, int s) {
        const uint32_t db = sb + s * STAGEB + drow;
        const size_t go = (size_t)c * 32;
        CP16(db + 0*TILEB,      Ahp + go);
        CP16(db + 0*TILEB + 16, Ahp + go + 8);
        CP16(db + 1*TILEB,      Amp + go);
        CP16(db + 1*TILEB + 16, Amp + go + 8);
        CP16(db + 2*TILEB,      Bhp + go);
        CP16(db + 2*TILEB + 16, Bhp + go + 8);
    };

    issue(0, 0); CPCOMMIT();
    issue(1, 1); CPCOMMIT();

    for (int c = 0; c < 16; ++c) {
        const int s = c % 3;
        if (c < 15) CPWAIT1(); else CPWAIT0();
        __syncthreads();
        if (c + 2 < 16) { issue(c + 2, (c + 2) % 3); CPCOMMIT(); }

        const uint32_t aHi  = sb + s*STAGEB;
        const uint32_t aMid = aHi + TILEB;
        const uint32_t bHi  = aHi + 2*TILEB;

        #pragma unroll
        for (int kk = 0; kk < 32; kk += 16) {
            uint32_t ah[2][4], am[2][4], bh[8][2];
            // A-hi + B-hi fragments first
            #pragma unroll
            for (int mt = 0; mt < 2; mt++)
                LDMX4(ah[mt][0], ah[mt][1], ah[mt][2], ah[mt][3],
                      aHi + aoA + (uint32_t)(mt*16*ROWB + kk*2));
            #pragma unroll
            for (int np = 0; np < 4; np++) {
                uint32_t r0, r1, r2, r3;
                LDMX4(r0, r1, r2, r3, bHi + aoB + (uint32_t)(np*16*ROWB + kk*2));
                bh[2*np][0]   = r0; bh[2*np][1]   = r2;
                bh[2*np+1][0] = r1; bh[2*np+1][1] = r3;
            }
            // pass 1: hi_A * hi_B
            #pragma unroll
            for (int nt = 0; nt < 8; nt++)
                #pragma unroll
                for (int mt = 0; mt < 2; mt++)
                    MMA16816(acc[mt][nt], ah[mt], bh[nt]);
            // A-mid fragments loaded under pass-1 shadow
            #pragma unroll
            for (int mt = 0; mt < 2; mt++)
                LDMX4(am[mt][0], am[mt][1], am[mt][2], am[mt][3],
                      aMid + aoA + (uint32_t)(mt*16*ROWB + kk*2));
            // pass 2: mid_A * hi_B
            #pragma unroll
            for (int nt = 0; nt < 8; nt++)
                #pragma unroll
                for (int mt = 0; mt < 2; mt++)
                    MMA16816(acc[mt][nt], am[mt], bh[nt]);
        }
    }

    if (qkT && nblk < 2) {
        // ---- transposed epilogue: stage tile in smem, write channel-major ----
        __syncthreads();                       // all warps done with pipeline smem
        float* S = (float*)smem;               // S[128 cols][132]
        #pragma unroll
        for (int mt = 0; mt < 2; mt++) {
            const int lrow = wm*32 + mt*16 + g;
            #pragma unroll
            for (int nt = 0; nt < 8; nt++) {
                const int lcol = wn*64 + nt*8 + tg*2;
                const float bb0 = bias[ncol0 + lcol];
                const float bb1 = bias[ncol0 + lcol + 1];
                S[lcol*132     + lrow]     = acc[mt][nt][0] + bb0;
                S[(lcol+1)*132 + lrow]     = acc[mt][nt][1] + bb1;
                S[lcol*132     + lrow + 8] = acc[mt][nt][2] + bb0;
                S[(lcol+1)*132 + lrow + 8] = acc[mt][nt][3] + bb1;
            }
        }
        __syncthreads();
        const int bb = m0 >> 10;
        const int tb = m0 & 1023;
        float* dst = outF + ((size_t)bb * D_ + ncol0) * (size_t)L_ + tb;
        #pragma unroll
        for (int cc = 0; cc < 16; ++cc) {
            const int c2 = wid*16 + cc;
            float4 v4 = *(const float4*)&S[c2*132 + lane*4];
            *(float4*)&dst[(size_t)c2 * L_ + lane*4] = v4;
        }
        return;
    }

    // ---- normal epilogue ----
    #pragma unroll
    for (int mt = 0; mt < 2; mt++) {
        const int row0 = m0 + wm*32 + mt*16 + g;
        #pragma unroll
        for (int nt = 0; nt < 8; nt++) {
            const int col = ncol0 + wn*64 + nt*8 + tg*2;
            float bb0 = 0.f, bb1 = 0.f;
            if (bias) { bb0 = bias[col]; bb1 = bias[col + 1]; }
            float2 v0 = make_float2(acc[mt][nt][0] + bb0, acc[mt][nt][1] + bb1);
            float2 v1 = make_float2(acc[mt][nt][2] + bb0, acc[mt][nt][3] + bb1);
            const size_t i0 = (size_t)row0 * D_ + col;
            const size_t i1 = (size_t)(row0 + 8) * D_ + col;
            if (res) {
                float2 r0 = *(const float2*)&res[i0];
                float2 r1 = *(const float2*)&res[i1];
                v0.x += r0.x; v0.y += r0.y;
                v1.x += r1.x; v1.y += r1.y;
            }
            *(float2*)&outF[i0] = v0;
            *(float2*)&outF[i1] = v1;
        }
    }
}

// ---------------- x -> hi/mid fp16 split ----------------
__global__ void xsplit_kernel(const float* __restrict__ X,
                              __half* __restrict__ H, __half* __restrict__ M)
{
    const size_t i = (size_t)blockIdx.x * blockDim.x + threadIdx.x;
    float4 v = ((const float4*)X)[i];
    split2_store(make_float2(v.x, v.y), H, M, i*4);
    split2_store(make_float2(v.z, v.w), H, M, i*4 + 2);
}

// ------- merged weight transpose + fp16 hi (grid.z selects weight) -------------
__global__ void wtsplit_kernel(const float* __restrict__ W0, const float* __restrict__ W1,
                               const float* __restrict__ W2, const float* __restrict__ W3,
                               const float* __restrict__ W4,
                               __half* __restrict__ oh)
{
    const int z = blockIdx.z;
    const float* in = (z == 0) ? W0 : (z == 1) ? W1 : (z == 2) ? W2 : (z == 3) ? W3 : W4;
    oh += (size_t)z * D_ * D_;
    __shared__ float t[32][33];
    const int bx = blockIdx.x * 32, by = blockIdx.y * 32;
    const int tx = threadIdx.x, ty = threadIdx.y;
    #pragma unroll
    for (int r = 0; r < 32; r += 8)
        t[ty + r][tx] = in[(size_t)(by + ty + r) * D_ + bx + tx];
    __syncthreads();
    #pragma unroll
    for (int r = 0; r < 32; r += 8) {
        float v = t[tx][ty + r];
        oh[(size_t)(bx + ty + r) * D_ + by + tx] = __float2half_rn(v);
    }
}

// ---------------- FFT machinery ----------------
__global__ void twiddle_kernel()
{
    int j = blockIdx.x * 256 + threadIdx.x;
    double a = -2.0 * 3.14159265358979323846 * (double)j / (double)NFFT;
    g_twid[j] = make_float2((float)cos(a), (float)sin(a));
}
__global__ void zeroS_kernel() { g_S[blockIdx.x * 1024 + threadIdx.x] = 0.0f; }

__device__ __forceinline__ int brev10(int x) { return (int)(__brev((uint32_t)x) >> 22); }
__device__ __forceinline__ float2 cadd(float2 a, float2 b) { return make_float2(a.x+b.x, a.y+b.y); }
__device__ __forceinline__ float2 csub(float2 a, float2 b) { return make_float2(a.x-b.x, a.y-b.y); }
__device__ __forceinline__ float2 cmul(float2 a, float2 w) {
    return make_float2(a.x*w.x - a.y*w.y, a.x*w.y + a.y*w.x);
}
__device__ __forceinline__ float2 cmulc(float2 a, float2 w) {
    return make_float2(a.x*w.x + a.y*w.y, a.y*w.x - a.x*w.y);
}

// forward: Z_c = FFT(q_c + i*k_c), 8 channels/block; inputs channel-major.
__global__ __launch_bounds__(256)
void fft_fwd_kernel(const float* __restrict__ QT, const float* __restrict__ KT)
{
    extern __shared__ __align__(16) float2 Z[];    // 8 * 1024
    __shared__ float2 tw[NFFT/2];
    const int tid = threadIdx.x;
    const int c0  = blockIdx.x * 8;
    const int b   = blockIdx.y;

    for (int i = tid; i < NFFT/2; i += 256) tw[i] = g_twid[i];

    const float* Qb = QT + ((size_t)b * D_ + c0) * (size_t)NFFT;
    const float* Kb = KT + ((size_t)b * D_ + c0) * (size_t)NFFT;
    for (int i = tid; i < 8 * (NFFT/4); i += 256) {
        const int cc = i >> 8;
        const int j  = (i & 255) * 4;
        float4 q4 = *(const float4*)&Qb[(size_t)cc * NFFT + j];
        float4 k4 = *(const float4*)&Kb[(size_t)cc * NFFT + j];
        float2* Zc = &Z[cc * NFFT + j];
        Zc[0] = make_float2(q4.x, k4.x);
        Zc[1] = make_float2(q4.y, k4.y);
        Zc[2] = make_float2(q4.z, k4.z);
        Zc[3] = make_float2(q4.w, k4.w);
    }
    __syncthreads();

    #pragma unroll
    for (int st = 0; st < 10; st += 2) {
        const int m = 512 >> st;
        const int h = m >> 1;
        for (int i = tid; i < 8 * 256; i += 256) {
            const int col = i >> 8;
            const int gi  = i & 255;
            const int j   = gi & (h - 1);
            const int gg  = gi >> (8 - st);
            const int base = col * NFFT + (gg << (10 - st)) + j;
            float2 e0 = Z[base], e1 = Z[base + h], e2 = Z[base + m], e3 = Z[base + m + h];
            float2 wa = tw[j << st];
            float2 wb = tw[(j + h) << st];
            float2 wc = tw[j << (st + 1)];
            float2 u0 = cadd(e0, e2), v0 = cmul(csub(e0, e2), wa);
            float2 u1 = cadd(e1, e3), v1 = cmul(csub(e1, e3), wb);
            Z[base]         = cadd(u0, u1);
            Z[base + h]     = cmul(csub(u0, u1), wc);
            Z[base + m]     = cadd(v0, v1);
            Z[base + m + h] = cmul(csub(v0, v1), wc);
        }
        __syncthreads();
    }

    for (int f = tid; f < NFFT; f += 256) {
        const int p  = brev10(f);
        const int pn = brev10((NFFT - f) & (NFFT - 1));
        float sx = 0.f, sy = 0.f;
        #pragma unroll
        for (int cc = 0; cc < 8; cc++) {
            float2 z1 = Z[cc * NFFT + p];
            float2 z2 = Z[cc * NFFT + pn];
            float Qx = 0.5f * (z1.x + z2.x), Qy = 0.5f * (z1.y - z2.y);
            float wx = z1.x - z2.x,          wy = z1.y + z2.y;
            float Kx = 0.5f * wy,            Ky = -0.5f * wx;
            sx += Qx * Kx + Qy * Ky;
            sy += Qy * Kx - Qx * Ky;
        }
        atomicAdd(&g_S[(b * NFFT + f) * 2    ], sx);
        atomicAdd(&g_S[(b * NFFT + f) * 2 + 1], sy);
    }
}

// ---- fused inverse FFT + top-13 + softmax: one block per batch ---------------
__global__ __launch_bounds__(256)
void fft_inv_topk_kernel(int* __restrict__ delays, float* __restrict__ w)
{
    __shared__ float2 Zs[NFFT];
    __shared__ float2 tw[NFFT/2];
    __shared__ float vals[L_];
    __shared__ float rv[256];
    __shared__ int   ri[256];
    __shared__ float topv[TOPK_];
    __shared__ int   topi[TOPK_];
    const int tid = threadIdx.x;
    const int b   = blockIdx.x;
    for (int i = tid; i < NFFT/2; i += 256) tw[i] = g_twid[i];
    for (int i = tid; i < NFFT; i += 256)
        Zs[i] = make_float2(g_S[(b * NFFT + i) * 2], g_S[(b * NFFT + i) * 2 + 1]);
    __syncthreads();

    #pragma unroll
    for (int st = 0; st < 10; st += 2) {
        const int m = 512 >> st;
        const int h = m >> 1;
        for (int gi = tid; gi < 256; gi += 256) {
            const int j  = gi & (h - 1);
            const int gg = gi >> (8 - st);
            const int base = (gg << (10 - st)) + j;
            float2 e0 = Zs[base], e1 = Zs[base + h], e2 = Zs[base + m], e3 = Zs[base + m + h];
            float2 wa = tw[j << st];
            float2 wb = tw[(j + h) << st];
            float2 wc = tw[j << (st + 1)];
            float2 u0 = cadd(e0, e2), v0 = cmulc(csub(e0, e2), wa);
            float2 u1 = cadd(e1, e3), v1 = cmulc(csub(e1, e3), wb);
            Zs[base]         = cadd(u0, u1);
            Zs[base + h]     = cmulc(csub(u0, u1), wc);
            Zs[base + m]     = cadd(v0, v1);
            Zs[base + m + h] = cmulc(csub(v0, v1), wc);
        }
        __syncthreads();
    }
    const float scale = 1.0f / ((float)NFFT * (float)D_);
    for (int p = tid; p < NFFT; p += 256)
        vals[brev10(p)] = Zs[p].x * scale;
    __syncthreads();

    for (int sel = 0; sel < TOPK_; sel++) {
        float bv = -FLT_MAX;
        int   bi = 1 << 30;
        for (int i = tid; i < L_; i += 256) {
            float v = vals[i];
            if (v > bv || (v == bv && i < bi)) { bv = v; bi = i; }
        }
        rv[tid] = bv; ri[tid] = bi;
        __syncthreads();
        for (int s = 128; s > 0; s >>= 1) {
            if (tid < s) {
                if (rv[tid+s] > rv[tid] || (rv[tid+s] == rv[tid] && ri[tid+s] < ri[tid])) {
                    rv[tid] = rv[tid+s]; ri[tid] = ri[tid+s];
                }
            }
            __syncthreads();
        }
        if (tid == 0) {
            topv[sel] = rv[0];
            topi[sel] = ri[0];
            vals[ri[0]] = -FLT_MAX;
        }
        __syncthreads();
    }

    if (tid == 0) {
        float mx = topv[0];
        float e[TOPK_], se = 0.0f;
        #pragma unroll
        for (int i = 0; i < TOPK_; i++) { e[i] = expf(topv[i] - mx); se += e[i]; }
        float inv = 1.0f / se;
        #pragma unroll
        for (int i = 0; i < TOPK_; i++) {
            w[b*TOPK_ + i]      = e[i] * inv;
            delays[b*TOPK_ + i] = topi[i];
        }
    }
}

// ------- aggregation, 16 t per block: agg = sum_i w_i * V[(t+d_i)%L], split out
__global__ void aggregate_kernel(const float* __restrict__ V,
                                 const int* __restrict__ delays,
                                 const float* __restrict__ w,
                                 __half* __restrict__ Oh,
                                 __half* __restrict__ Om)
{
    const int t0 = blockIdx.x * 16;
    const int b  = blockIdx.y;
    const int c  = threadIdx.x;
    __shared__ int   sd[TOPK_];
    __shared__ float sw[TOPK_];
    if (c < TOPK_) { sd[c] = delays[b*TOPK_ + c]; sw[c] = w[b*TOPK_ + c]; }
    __syncthreads();

    const float4* V4 = (const float4*)V + (size_t)b * L_ * (D_/4);
    for (int tt = 0; tt < 16; ++tt) {
        const int t = t0 + tt;
        float4 acc = make_float4(0.f, 0.f, 0.f, 0.f);
        #pragma unroll
        for (int i = 0; i < TOPK_; i++) {
            int row = (t + sd[i]) & (L_ - 1);
            float4 vv = V4[(size_t)row * (D_/4) + c];
            float wi = sw[i];
            acc.x = fmaf(wi, vv.x, acc.x);
            acc.y = fmaf(wi, vv.y, acc.y);
            acc.z = fmaf(wi, vv.z, acc.z);
            acc.w = fmaf(wi, vv.w, acc.w);
        }
        const size_t e = ((size_t)(b * L_ + t) * (D_/4) + c) * 4;
        split2_store(make_float2(acc.x, acc.y), Oh, Om, e);
        split2_store(make_float2(acc.z, acc.w), Oh, Om, e + 2);
    }
}

// ---- season = X - moving_average(X,25) via per-thread sliding window ----------
__global__ void movavg_kernel(const float* __restrict__ X, float* __restrict__ OutF,
                              __half* __restrict__ OutH, __half* __restrict__ OutM)
{
    const int seg = blockIdx.x;
    const int b   = blockIdx.y;
    const int c   = threadIdx.x;
    const float4* Xb = (const float4*)X + (size_t)b * L_ * 128;
    const int t0 = seg * 64;

    float sx = 0.f, sy = 0.f, sz = 0.f, sw = 0.f;
    const int lo0 = max(t0 - 12, 0), hi0 = min(t0 + 12, L_ - 1);
    for (int ss = lo0; ss <= hi0; ++ss) {
        float4 v = Xb[(size_t)ss * 128 + c];
        sx += v.x; sy += v.y; sz += v.z; sw += v.w;
    }
    for (int t = t0; t < t0 + 64; ++t) {
        const int lo = max(t - 12, 0), hi = min(t + 12, L_ - 1);
        const float inv = 1.0f / (float)(hi - lo + 1);
        float4 xv = Xb[(size_t)t * 128 + c];
        float4 o;
        o.x = xv.x - sx * inv;
        o.y = xv.y - sy * inv;
        o.z = xv.z - sz * inv;
        o.w = xv.w - sw * inv;
        const size_t oi = (size_t)(b * L_ + t) * 128 + c;
        ((float4*)OutF)[oi] = o;
        if (OutH) {
            split2_store(make_float2(o.x, o.y), OutH, OutM, oi * 4);
            split2_store(make_float2(o.z, o.w), OutH, OutM, oi * 4 + 2);
        }
        if (t + 13 <= L_ - 1) {
            float4 v = Xb[(size_t)(t + 13) * 128 + c];
            sx += v.x; sy += v.y; sz += v.z; sw += v.w;
        }
        if (t - 12 >= 0) {
            float4 v = Xb[(size_t)(t - 12) * 128 + c];
            sx -= v.x; sy -= v.y; sz -= v.z; sw -= v.w;
        }
    }
}

// ---------------- host launch ----------------
extern "C" void kernel_launch(void* const* d_in, const int* in_sizes, int n_in,
                              void* d_out, int out_size)
{
    const float* x  = (const float*)d_in[0];
    const float* Wq = (const float*)d_in[1];
    const float* bq = (const float*)d_in[2];
    const float* Wk = (const float*)d_in[3];
    const float* bk = (const float*)d_in[4];
    const float* Wv = (const float*)d_in[5];
    const float* bv = (const float*)d_in[6];
    const float* Wo = (const float*)d_in[7];
    const float* bo = (const float*)d_in[8];
    const float* Wd = (const float*)d_in[9];
    const float* bd = (const float*)d_in[10];
    float* out = (float*)d_out;

    float *v, *qT, *kT, *x1, *s1, *x2, *w;
    int* dl;
    __half *xh, *xm, *ah, *am, *sh, *sm, *wth;
    cudaGetSymbolAddress((void**)&v,    g_v);
    cudaGetSymbolAddress((void**)&qT,   g_qT);
    cudaGetSymbolAddress((void**)&kT,   g_kT);
    cudaGetSymbolAddress((void**)&x1,   g_x1);
    cudaGetSymbolAddress((void**)&s1,   g_s1);
    cudaGetSymbolAddress((void**)&x2,   g_x2);
    cudaGetSymbolAddress((void**)&dl,   g_delay);
    cudaGetSymbolAddress((void**)&w,    g_w);
    cudaGetSymbolAddress((void**)&xh,   g_xh);  cudaGetSymbolAddress((void**)&xm, g_xm);
    cudaGetSymbolAddress((void**)&ah,   g_ah);  cudaGetSymbolAddress((void**)&am, g_am);
    cudaGetSymbolAddress((void**)&sh,   g_sh);  cudaGetSymbolAddress((void**)&sm, g_sm);
    cudaGetSymbolAddress((void**)&wth,  g_wth);

    cudaFuncSetAttribute(gemm_hf, cudaFuncAttributeMaxDynamicSharedMemorySize, SMEM_MMA);
    cudaFuncSetAttribute(fft_fwd_kernel, cudaFuncAttributeMaxDynamicSharedMemorySize, 8*NFFT*8);

    // input splits + twiddles
    xsplit_kernel<<<NEL_/4/256, 256>>>(x, xh, xm);
    dim3 tT(32, 8), gT(16, 16, 5);
    wtsplit_kernel<<<gT, tT>>>(Wq, Wk, Wv, Wo, Wd, wth);
    twiddle_kernel<<<2, 256>>>();

    dim3 t256(256);
    dim3 gQKV(3*D_/128, (B_*L_)/128);     // (12, 256) fused QKV
    dim3 gdense(D_/128, (B_*L_)/128);     // (4, 256)

    // fused Q/K/V projection; Q,K written channel-major for the FFT
    gemm_hf<<<gQKV, t256, SMEM_MMA>>>(xh, xm, wth, bq, bk, bv, nullptr, qT, kT, v, 1);

    // FFT autocorrelation
    zeroS_kernel<<<B_*2, 1024>>>();
    dim3 gfft(D_/8, B_);
    fft_fwd_kernel<<<gfft, 256, 8*NFFT*8>>>(qT, kT);

    // fused inverse FFT + top-13 + softmax
    fft_inv_topk_kernel<<<B_, 256>>>(dl, w);

    // delay aggregation of V -> fp16 split agg (16 t per block)
    dim3 gld(L_/16, B_);
    aggregate_kernel<<<gld, 128>>>(v, dl, w, ah, am);

    // x1 = agg @ Wo + bo + x
    gemm_hf<<<gdense, t256, SMEM_MMA>>>(ah, am, wth + 3*D_*D_,
                                        bo, bo, bo, x, x1, x1, x1, 0);

    // s1 = x1 - movavg(x1), plus fp16 split s1
    dim3 gma(16, B_);
    movavg_kernel<<<gma, 128>>>(x1, s1, sh, sm);

    // x2 = s1 @ Wd + bd + s1
    gemm_hf<<<gdense, t256, SMEM_MMA>>>(sh, sm, wth + 4*D_*D_,
                                        bd, bd, bd, s1, x2, x2, x2, 0);

    // out = x2 - movavg(x2)
    movavg_kernel<<<gma, 128>>>(x2, out, nullptr, nullptr);
}